// round 12
// baseline (speedup 1.0000x reference)
#include <cuda_runtime.h>
#include <cuda_fp16.h>
#include <cstdint>

#define SEQ 1024
#define DIMC 1024
#define NHEADS 16
#define HDIM 64
#define NBATCH 2
#define NBH (NBATCH*NHEADS)   // 32

// ---------------- scratch (device globals; no runtime allocation) -------------
__device__ float    g_v[NBH][SEQ][HDIM];        // 8 MB  v fp32 (dwc epilogue)
__device__ __half   g_vh[NBH][SEQ][HDIM];       // 4 MB  v fp16 (mma operand)
__device__ uint32_t g_qkT[2][NBH][32][1024];    // 8 MB  q,k transposed: [d2][s] half2
__device__ __half   g_xh[2048*1024];            // fp16 x
__device__ __half   g_wqh[3072*1024];           // fp16 qkv_w
__device__ __half   g_wph[1024*1024];           // fp16 proj_w
__device__ __half   g_yh[2048*1024];            // fp16 pre-projection activations

// ---------------- helpers ------------------------------------------------------
__device__ __forceinline__ uint32_t smem_u32(const void* p) {
    return (uint32_t)__cvta_generic_to_shared(p);
}
__device__ __forceinline__ void cp16(uint32_t s, const void* g) {
    asm volatile("cp.async.cg.shared.global [%0], [%1], 16;\n" :: "r"(s), "l"(g));
}
__device__ __forceinline__ void mma_f16(float c[4],
        uint32_t a0, uint32_t a1, uint32_t a2, uint32_t a3,
        uint32_t b0, uint32_t b1) {
    asm volatile(
        "mma.sync.aligned.m16n8k16.row.col.f32.f16.f16.f32 "
        "{%0,%1,%2,%3}, {%4,%5,%6,%7}, {%8,%9}, {%0,%1,%2,%3};"
        : "+f"(c[0]), "+f"(c[1]), "+f"(c[2]), "+f"(c[3])
        : "r"(a0), "r"(a1), "r"(a2), "r"(a3), "r"(b0), "r"(b1));
}
__device__ __forceinline__ void ldsm4(uint32_t& r0, uint32_t& r1,
                                      uint32_t& r2, uint32_t& r3, uint32_t a) {
    asm volatile("ldmatrix.sync.aligned.m8n8.x4.shared.b16 {%0,%1,%2,%3}, [%4];"
                 : "=r"(r0), "=r"(r1), "=r"(r2), "=r"(r3) : "r"(a));
}
__device__ __forceinline__ void ldsm4t(uint32_t& r0, uint32_t& r1,
                                       uint32_t& r2, uint32_t& r3, uint32_t a) {
    asm volatile("ldmatrix.sync.aligned.m8n8.x4.trans.shared.b16 {%0,%1,%2,%3}, [%4];"
                 : "=r"(r0), "=r"(r1), "=r"(r2), "=r"(r3) : "r"(a));
}
__device__ __forceinline__ uint32_t h2u(__half2 h) { return *(uint32_t*)&h; }
__device__ __forceinline__ __half2 u2h(uint32_t u) { return *(__half2*)&u; }

// ==============================================================================
// Prepass: convert x / qkv_w / proj_w to fp16 scratch copies.
// ==============================================================================
__global__ __launch_bounds__(256) void prep_f16(const float* __restrict__ x,
                                                const float* __restrict__ wq,
                                                const float* __restrict__ wp)
{
    const float4* src; __half* dh; int n4;
    if (blockIdx.y == 0)      { src = (const float4*)x;  dh = g_xh;  n4 = 524288; }
    else if (blockIdx.y == 1) { src = (const float4*)wq; dh = g_wqh; n4 = 786432; }
    else                      { src = (const float4*)wp; dh = g_wph; n4 = 262144; }
    int i = blockIdx.x * 256 + threadIdx.x;
    if (i < n4) {
        float4 v = src[i];
        ((uint2*)dh)[i] = make_uint2(h2u(__floats2half2_rn(v.x, v.y)),
                                     h2u(__floats2half2_rn(v.z, v.w)));
    }
}

// ==============================================================================
// fp16 tensor-core GEMM (NT), BM=128 BN=64 BK=32, 3-stage cp.async, occ 3.
// 8 warps: 4M x 2N, warp tile 32x32.
// MODE 1: A=x, B=qkv_w; q,k -> g_qkT (transposed half2), v -> g_v + g_vh.
// MODE 0: A=y, B=proj_w, row-major fp32 C.
// stage: A 128x80B (10240) | B 64x80B (5120) = 15360; x3 stages.
// ==============================================================================
#define HG_STAGE 15360
#define HG_SMEM  (3*HG_STAGE)

template<int MODE>
__global__ __launch_bounds__(256, 3) void hgemm_nt(
    const float* __restrict__ bias, float* __restrict__ C, int N, int K)
{
    extern __shared__ char smh[];
    const uint32_t smB = smem_u32(smh);

    const int tid  = threadIdx.x;
    const int warp = tid >> 5;
    const int lane = tid & 31;
    const int gr   = lane >> 2;
    const int tg   = lane & 3;
    const int wm   = (warp & 3) * 32;
    const int wn   = (warp >> 2) * 32;
    const int mb   = blockIdx.y * 128;
    const int nb   = blockIdx.x * 64;

    const __half* AH = (MODE == 1) ? g_xh  : g_yh;
    const __half* BH = (MODE == 1) ? g_wqh : g_wph;

    // staging coords
    const int rowA = tid >> 1, cpA = (tid & 1) * 2;         // 2 chunks per thread
    const int rowB = tid >> 2, chB = tid & 3;               // 1 chunk per thread
    const __half* aHg = AH + (size_t)(mb + rowA) * K + cpA * 8;
    const __half* bHg = BH + (size_t)(nb + rowB) * K + chB * 8;
    const uint32_t stA = rowA * 80 + cpA * 16;
    const uint32_t stB = 10240 + rowB * 80 + chB * 16;

    auto load_st = [&](int st, int k0) {
        const uint32_t d = smB + st * HG_STAGE;
        cp16(d + stA,      aHg + k0);
        cp16(d + stA + 16, aHg + k0 + 8);
        cp16(d + stB,      bHg + k0);
        asm volatile("cp.async.commit_group;\n");
    };

    float acc[2][4][4];
#pragma unroll
    for (int i = 0; i < 2; i++)
#pragma unroll
        for (int j = 0; j < 4; j++)
#pragma unroll
            for (int r = 0; r < 4; r++) acc[i][j][r] = 0.f;

    const uint32_t aOff = (wm + (lane & 15)) * 80 + (lane >> 4) * 16;
    const uint32_t bOff = 10240 + (wn + (lane & 15)) * 80 + (lane >> 4) * 16;

    const int nK = K / 32;
    load_st(0, 0);
    load_st(1, 32);

    for (int kt = 0; kt < nK; kt++) {
        asm volatile("cp.async.wait_group 1;\n");
        __syncthreads();
        if (kt + 2 < nK) load_st((kt + 2) % 3, (kt + 2) * 32);
        const uint32_t sb = smB + (kt % 3) * HG_STAGE;

#pragma unroll
        for (int s = 0; s < 2; s++) {
            uint32_t ah[2][4];
#pragma unroll
            for (int i = 0; i < 2; i++)
                ldsm4(ah[i][0], ah[i][1], ah[i][2], ah[i][3],
                      sb + aOff + i * 1280 + s * 32);
#pragma unroll
            for (int j = 0; j < 2; j++) {
                uint32_t bh_[4];
                ldsm4(bh_[0], bh_[1], bh_[2], bh_[3],
                      sb + bOff + j * 1280 + s * 32);
#pragma unroll
                for (int i = 0; i < 2; i++) {
                    mma_f16(acc[i][2*j  ], ah[i][0], ah[i][1], ah[i][2], ah[i][3], bh_[0], bh_[2]);
                    mma_f16(acc[i][2*j+1], ah[i][0], ah[i][1], ah[i][2], ah[i][3], bh_[1], bh_[3]);
                }
            }
        }
        __syncthreads();
    }

#pragma unroll
    for (int i = 0; i < 2; i++) {
#pragma unroll
        for (int j = 0; j < 4; j++) {
            const int r0 = mb + wm + i * 16 + gr;
            const int c0 = nb + wn + j * 8 + 2 * tg;     // even
            const float bia0 = bias[c0], bia1 = bias[c0 + 1];
            if (MODE == 1) {
                const int tsel = c0 >> 10, rem = c0 & 1023;
                const int hh = rem >> 6, d = rem & 63;
#pragma unroll
                for (int pr = 0; pr < 2; pr++) {
                    const int m = r0 + pr * 8;
                    const int bb = m >> 10, s = m & 1023;
                    const int bh2 = bb * NHEADS + hh;
                    const float v0 = acc[i][j][pr*2 + 0] + bia0;
                    const float v1 = acc[i][j][pr*2 + 1] + bia1;
                    const uint32_t pk = h2u(__floats2half2_rn(v0, v1));
                    if (tsel < 2) {
                        g_qkT[tsel][bh2][d >> 1][s] = pk;
                    } else {
                        *(float2*)&g_v[bh2][s][d] = make_float2(v0, v1);
                        *(uint32_t*)&g_vh[bh2][s][d] = pk;
                    }
                }
            } else {
                float2 lo = make_float2(acc[i][j][0] + bia0, acc[i][j][1] + bia1);
                float2 hi = make_float2(acc[i][j][2] + bia0, acc[i][j][3] + bia1);
                *(float2*)&C[(size_t)r0 * N + c0]       = lo;
                *(float2*)&C[(size_t)(r0 + 8) * N + c0] = hi;
            }
        }
    }
}

// ==============================================================================
// FUSED Laplacian + attn@v + rownorm + depthwise conv. (proven round-11)
// ==============================================================================
#define QS_OFF   0
#define KS_OFF   8704
#define KT_OFF   26112
#define VH_OFF   35328
#define RS_OFF   53760
#define LAP_SMEM 54016

__global__ __launch_bounds__(256, 4) void lap_av(const float* __restrict__ dwc_w,
                                                 const float* __restrict__ dwc_b)
{
    extern __shared__ char sm[];
    const uint32_t smB = smem_u32(sm);

    const int tid  = threadIdx.x;
    const int tx   = tid & 15;
    const int ty   = tid >> 4;
    const int warp = tid >> 5;
    const int lane = tid & 31;
    const int gr   = lane >> 2;
    const int tg   = lane & 3;
    const int wm4  = (warp & 3) * 16;
    const int wn2  = (warp >> 2) * 32;
    const int it   = blockIdx.x;
    const int bh   = blockIdx.y;
    const int bb   = bh >> 4;
    const int h    = bh & 15;

    const char* Qt = (const char*)&g_qkT[0][bh][0][0];
    const char* Kt = (const char*)&g_qkT[1][bh][0][0];
    const __half* Vh = &g_vh[bh][0][0];
    const float*  V  = &g_v[bh][0][0];

    auto stage_q = [&]() {
#pragma unroll
        for (int r = 0; r < 2; r++) {
            int idx = tid + r * 256;
            int d2 = idx >> 4, c = idx & 15;
            cp16(smB + QS_OFF + d2 * 272 + c * 16,
                 Qt + ((size_t)d2 * 1024 + it * 64 + c * 4) * 4);
        }
    };
    auto stage_k = [&](int buf, int jt) {
#pragma unroll
        for (int r = 0; r < 2; r++) {
            int idx = tid + r * 256;
            int d2 = idx >> 4, c = idx & 15;
            cp16(smB + KS_OFF + buf * 8704 + d2 * 272 + c * 16,
                 Kt + ((size_t)d2 * 1024 + jt * 64 + c * 4) * 4);
        }
    };
    auto stage_v = [&](int buf, int jt) {
#pragma unroll
        for (int r = 0; r < 2; r++) {
            int idx = tid + r * 256;
            int j = idx >> 3, c = idx & 7;
            cp16(smB + VH_OFF + buf * 9216 + j * 144 + c * 16,
                 (const char*)Vh + ((size_t)(jt * 64 + j) * 64 + c * 8) * 2);
        }
    };

    const uint32_t aKt = smB + KT_OFF
        + (wm4 + (lane & 7) + ((lane >> 3) & 1) * 8) * 144 + (lane >> 4) * 16;
    const uint32_t bVh = smB + VH_OFF
        + (lane & 15) * 144 + (lane >> 4) * 16 + wn2 * 2;

    stage_q(); stage_k(0, 0); stage_v(0, 0);
    asm volatile("cp.async.commit_group;\n");

    float rs[4] = {0.f, 0.f, 0.f, 0.f};
    float macc[4][4];
#pragma unroll
    for (int n = 0; n < 4; n++)
#pragma unroll
        for (int e = 0; e < 4; e++) macc[n][e] = 0.f;

    const uint32_t* qsP = (const uint32_t*)(sm + QS_OFF);

    for (int jt = 0; jt < 16; jt++) {
        const int buf = jt & 1;
        asm volatile("cp.async.wait_group 0;\n");
        __syncthreads();
        if (jt < 15) {
            stage_k(buf ^ 1, jt + 1);
            stage_v(buf ^ 1, jt + 1);
            asm volatile("cp.async.commit_group;\n");
        }

        const uint32_t* ksP = (const uint32_t*)(sm + KS_OFF + buf * 8704);
        __half2 acc[4][4];
#pragma unroll
        for (int ii = 0; ii < 4; ii++)
#pragma unroll
            for (int jj = 0; jj < 4; jj++)
                acc[ii][jj] = __half2half2(__ushort_as_half(0));

#pragma unroll
        for (int d2 = 0; d2 < 32; d2++) {
            uint4 qv = *(const uint4*)(qsP + d2 * 68 + ty * 4);
            uint4 kv = *(const uint4*)(ksP + d2 * 68 + tx * 4);
            uint32_t q2[4] = {qv.x, qv.y, qv.z, qv.w};
            uint32_t k2[4] = {kv.x, kv.y, kv.z, kv.w};
#pragma unroll
            for (int ii = 0; ii < 4; ii++)
#pragma unroll
                for (int jj = 0; jj < 4; jj++)
                    acc[ii][jj] = __hadd2(acc[ii][jj],
                                   __habs2(__hsub2(u2h(q2[ii]), u2h(k2[jj]))));
        }

#pragma unroll
        for (int ii = 0; ii < 4; ii++) {
            float op[4];
#pragma unroll
            for (int jj = 0; jj < 4; jj++) {
                float2 fa = __half22float2(acc[ii][jj]);
                float dist = fa.x + fa.y;
                float kv = __expf(-0.0625f * dist);
                op[jj] = kv;
                rs[ii] += kv;
            }
            *(uint2*)(sm + KT_OFF + (ty*4 + ii) * 144 + tx * 8)
                = make_uint2(h2u(__floats2half2_rn(op[0], op[1])),
                             h2u(__floats2half2_rn(op[2], op[3])));
        }
        __syncthreads();

        const uint32_t bB = bVh + buf * 9216;
#pragma unroll
        for (int k16 = 0; k16 < 4; k16++) {
            uint32_t a0, a1, a2, a3;
            ldsm4(a0, a1, a2, a3, aKt + k16 * 32);
#pragma unroll
            for (int nf2 = 0; nf2 < 2; nf2++) {
                uint32_t b0, b1, b2, b3;
                ldsm4t(b0, b1, b2, b3, bB + k16 * 2304 + nf2 * 32);
                mma_f16(macc[2*nf2    ], a0, a1, a2, a3, b0, b1);
                mma_f16(macc[2*nf2 + 1], a0, a1, a2, a3, b2, b3);
            }
        }
    }

    float* rsum = (float*)(sm + RS_OFF);
#pragma unroll
    for (int ii = 0; ii < 4; ii++) {
        float v = rs[ii];
        v += __shfl_xor_sync(0xffffffffu, v, 1);
        v += __shfl_xor_sync(0xffffffffu, v, 2);
        v += __shfl_xor_sync(0xffffffffu, v, 4);
        v += __shfl_xor_sync(0xffffffffu, v, 8);
        if (tx == 0) rsum[ty*4 + ii] = v;
    }
    __syncthreads();

#pragma unroll
    for (int nf = 0; nf < 4; nf++) {
        const int dl = wn2 + nf * 8 + tg * 2;
        const int c  = h * 64 + dl;
        const float w0a = dwc_w[c*3+0], w1a = dwc_w[c*3+1], w2a = dwc_w[c*3+2];
        const float b0a = dwc_b[c];
        const float w0b = dwc_w[c*3+3], w1b = dwc_w[c*3+4], w2b = dwc_w[c*3+5];
        const float b1b = dwc_b[c+1];
#pragma unroll
        for (int half = 0; half < 2; half++) {
            const int il = wm4 + gr + half * 8;
            const int s  = it * 64 + il;
            const float sc = 1.0f / (rsum[il] + 1e-6f);
            float o0 = macc[nf][half*2 + 0] * sc;
            float o1 = macc[nf][half*2 + 1] * sc;
            float2 v0 = *(const float2*)&V[(size_t)s*64 + dl];
            float2 vm = (s > 0)       ? *(const float2*)&V[(size_t)(s-1)*64 + dl]
                                      : make_float2(0.f, 0.f);
            float2 vp = (s < SEQ - 1) ? *(const float2*)&V[(size_t)(s+1)*64 + dl]
                                      : make_float2(0.f, 0.f);
            o0 += w0a*vm.x + w1a*v0.x + w2a*vp.x + b0a;
            o1 += w0b*vm.y + w1b*v0.y + w2b*vp.y + b1b;
            const size_t oidx = (size_t)(bb*SEQ + s) * 1024 + c;
            *(uint32_t*)&g_yh[oidx] = h2u(__floats2half2_rn(o0, o1));
        }
    }
}

// ==============================================================================
extern "C" void kernel_launch(void* const* d_in, const int* in_sizes, int n_in,
                              void* d_out, int out_size)
{
    const float* x      = (const float*)d_in[0];
    const float* qkv_w  = (const float*)d_in[1];
    const float* qkv_b  = (const float*)d_in[2];
    const float* proj_w = (const float*)d_in[3];
    const float* proj_b = (const float*)d_in[4];
    const float* dwc_w  = (const float*)d_in[5];
    const float* dwc_b  = (const float*)d_in[6];
    float* out = (float*)d_out;

    cudaFuncSetAttribute(hgemm_nt<1>, cudaFuncAttributeMaxDynamicSharedMemorySize, HG_SMEM);
    cudaFuncSetAttribute(hgemm_nt<0>, cudaFuncAttributeMaxDynamicSharedMemorySize, HG_SMEM);
    cudaFuncSetAttribute(lap_av,      cudaFuncAttributeMaxDynamicSharedMemorySize, LAP_SMEM);

    // 0) convert x / weights to fp16 scratch
    prep_f16<<<dim3(3072, 3), 256>>>(x, qkv_w, proj_w);
    // 1) qkv projection (fp16 HMMA, BN=64, 3-stage); q,k -> transposed, v -> fp32+fp16
    hgemm_nt<1><<<dim3(48, 16), 256, HG_SMEM>>>(qkv_b, nullptr, 3072, 1024);
    // 2) FUSED Laplacian kernel + attn@v + rownorm + dwc -> y (fp16)
    lap_av<<<dim3(16, 32), 256, LAP_SMEM>>>(dwc_w, dwc_b);
    // 3) output projection (fp16 HMMA, BN=64, 3-stage) -> d_out
    hgemm_nt<0><<<dim3(16, 16), 256, HG_SMEM>>>(proj_b, out, 1024, 1024);
}

// round 14
// speedup vs baseline: 1.4920x; 1.4920x over previous
#include <cuda_runtime.h>
#include <cuda_fp16.h>
#include <cstdint>

#define SEQ 1024
#define DIMC 1024
#define NHEADS 16
#define HDIM 64
#define NBATCH 2
#define NBH (NBATCH*NHEADS)   // 32

// ---------------- scratch (device globals; no runtime allocation) -------------
__device__ float    g_v[NBH][SEQ][HDIM];        // 8 MB  v fp32 (dwc epilogue)
__device__ __half   g_vh[NBH][SEQ][HDIM];       // 4 MB  v fp16 (mma operand)
__device__ uint32_t g_qk8[2][NBH][16][1024];    // 4 MB  q,k int8x4: [d4][s]
__device__ __half   g_xh[2048*1024];            // fp16 x
__device__ __half   g_wqh[3072*1024];           // fp16 qkv_w
__device__ __half   g_wph[1024*1024];           // fp16 proj_w
__device__ __half   g_yh[2048*1024];            // fp16 pre-projection activations

#define QSCALE     24.0f
#define KERN_COEF  (-2.6041667e-3f)   // -LAMBDA/HEAD_DIM/QSCALE = -0.0625/24

// ---------------- helpers ------------------------------------------------------
__device__ __forceinline__ uint32_t smem_u32(const void* p) {
    return (uint32_t)__cvta_generic_to_shared(p);
}
__device__ __forceinline__ void cp16(uint32_t s, const void* g) {
    asm volatile("cp.async.cg.shared.global [%0], [%1], 16;\n" :: "r"(s), "l"(g));
}
__device__ __forceinline__ void mma_f16(float c[4],
        uint32_t a0, uint32_t a1, uint32_t a2, uint32_t a3,
        uint32_t b0, uint32_t b1) {
    asm volatile(
        "mma.sync.aligned.m16n8k16.row.col.f32.f16.f16.f32 "
        "{%0,%1,%2,%3}, {%4,%5,%6,%7}, {%8,%9}, {%0,%1,%2,%3};"
        : "+f"(c[0]), "+f"(c[1]), "+f"(c[2]), "+f"(c[3])
        : "r"(a0), "r"(a1), "r"(a2), "r"(a3), "r"(b0), "r"(b1));
}
__device__ __forceinline__ void ldsm4(uint32_t& r0, uint32_t& r1,
                                      uint32_t& r2, uint32_t& r3, uint32_t a) {
    asm volatile("ldmatrix.sync.aligned.m8n8.x4.shared.b16 {%0,%1,%2,%3}, [%4];"
                 : "=r"(r0), "=r"(r1), "=r"(r2), "=r"(r3) : "r"(a));
}
__device__ __forceinline__ void ldsm4t(uint32_t& r0, uint32_t& r1,
                                       uint32_t& r2, uint32_t& r3, uint32_t a) {
    asm volatile("ldmatrix.sync.aligned.m8n8.x4.trans.shared.b16 {%0,%1,%2,%3}, [%4];"
                 : "=r"(r0), "=r"(r1), "=r"(r2), "=r"(r3) : "r"(a));
}
__device__ __forceinline__ uint32_t h2u(__half2 h) { return *(uint32_t*)&h; }
__device__ __forceinline__ __half2 u2h(uint32_t u) { return *(__half2*)&u; }

// ==============================================================================
// Prepass: convert x / qkv_w / proj_w to fp16 scratch copies.
// ==============================================================================
__global__ __launch_bounds__(256) void prep_f16(const float* __restrict__ x,
                                                const float* __restrict__ wq,
                                                const float* __restrict__ wp)
{
    const float4* src; __half* dh; int n4;
    if (blockIdx.y == 0)      { src = (const float4*)x;  dh = g_xh;  n4 = 524288; }
    else if (blockIdx.y == 1) { src = (const float4*)wq; dh = g_wqh; n4 = 786432; }
    else                      { src = (const float4*)wp; dh = g_wph; n4 = 262144; }
    int i = blockIdx.x * 256 + threadIdx.x;
    if (i < n4) {
        float4 v = src[i];
        ((uint2*)dh)[i] = make_uint2(h2u(__floats2half2_rn(v.x, v.y)),
                                     h2u(__floats2half2_rn(v.z, v.w)));
    }
}

// ==============================================================================
// fp16 tensor-core GEMM (NT), BM=128 BN=128 BK=32, 2-stage (round-11 proven).
// MODE 1 only here: A=x, B=qkv_w; q,k -> g_qk8 (int8 packed), v -> g_v + g_vh.
// ==============================================================================
#define HG_STAGE 20480
#define HG_SMEM  (2*HG_STAGE)

__global__ __launch_bounds__(256, 2) void hgemm_qkv(
    const float* __restrict__ bias, int N, int K)
{
    extern __shared__ char smh[];
    const uint32_t smB = smem_u32(smh);

    const int tid  = threadIdx.x;
    const int warp = tid >> 5;
    const int lane = tid & 31;
    const int gr   = lane >> 2;
    const int tg   = lane & 3;
    const int wm   = (warp & 3) * 32;
    const int wn   = (warp >> 2) * 64;
    const int mb   = blockIdx.y * 128;
    const int nb   = blockIdx.x * 128;

    const __half* AH = g_xh;
    const __half* BH = g_wqh;

    const int row = tid >> 1;
    const int cp  = (tid & 1) * 2;
    const __half* aHg = AH + (size_t)(mb + row) * K + cp * 8;
    const __half* bHg = BH + (size_t)(nb + row) * K + cp * 8;
    const uint32_t stDst = row * 80 + cp * 16;

    auto load_st = [&](int st, int k0) {
        const uint32_t d = smB + st * HG_STAGE + stDst;
        cp16(d,         aHg + k0); cp16(d + 16,         aHg + k0 + 8);
        cp16(d + 10240, bHg + k0); cp16(d + 10240 + 16, bHg + k0 + 8);
        asm volatile("cp.async.commit_group;\n");
    };

    float acc[2][8][4];
#pragma unroll
    for (int i = 0; i < 2; i++)
#pragma unroll
        for (int j = 0; j < 8; j++)
#pragma unroll
            for (int r = 0; r < 4; r++) acc[i][j][r] = 0.f;

    const uint32_t aOff = (wm + (lane & 15)) * 80 + (lane >> 4) * 16;
    const uint32_t bOff = (wn + (lane & 15)) * 80 + (lane >> 4) * 16 + 10240;

    const int nK = K / 32;
    load_st(0, 0);

    for (int kt = 0; kt < nK; kt++) {
        asm volatile("cp.async.wait_group 0;\n");
        __syncthreads();
        if (kt + 1 < nK) load_st((kt + 1) & 1, (kt + 1) * 32);
        const uint32_t sb = smB + (kt & 1) * HG_STAGE;

#pragma unroll
        for (int s = 0; s < 2; s++) {
            uint32_t ah[2][4];
#pragma unroll
            for (int i = 0; i < 2; i++)
                ldsm4(ah[i][0], ah[i][1], ah[i][2], ah[i][3],
                      sb + aOff + i * 1280 + s * 32);
#pragma unroll
            for (int j = 0; j < 4; j++) {
                uint32_t bh_[4];
                ldsm4(bh_[0], bh_[1], bh_[2], bh_[3],
                      sb + bOff + j * 1280 + s * 32);
#pragma unroll
                for (int i = 0; i < 2; i++) {
                    mma_f16(acc[i][2*j  ], ah[i][0], ah[i][1], ah[i][2], ah[i][3], bh_[0], bh_[2]);
                    mma_f16(acc[i][2*j+1], ah[i][0], ah[i][1], ah[i][2], ah[i][3], bh_[1], bh_[3]);
                }
            }
        }
    }

#pragma unroll
    for (int i = 0; i < 2; i++) {
#pragma unroll
        for (int j = 0; j < 8; j++) {
            const int r0 = mb + wm + i * 16 + gr;
            const int c0 = nb + wn + j * 8 + 2 * tg;     // even
            const float bia0 = bias[c0], bia1 = bias[c0 + 1];
            const int tsel = c0 >> 10, rem = c0 & 1023;
            const int hh = rem >> 6, d = rem & 63;
#pragma unroll
            for (int pr = 0; pr < 2; pr++) {
                const int m = r0 + pr * 8;
                const int bb = m >> 10, s = m & 1023;
                const int bh2 = bb * NHEADS + hh;
                const float v0 = acc[i][j][pr*2 + 0] + bia0;
                const float v1 = acc[i][j][pr*2 + 1] + bia1;
                if (tsel < 2) {
                    int i0 = __float2int_rn(fminf(fmaxf(v0 * QSCALE, -127.f), 127.f));
                    int i1 = __float2int_rn(fminf(fmaxf(v1 * QSCALE, -127.f), 127.f));
                    unsigned short pk8 = (unsigned short)((i0 & 0xFF) | ((i1 & 0xFF) << 8));
                    *(unsigned short*)((char*)&g_qk8[tsel][bh2][d >> 2][s] + (d & 3)) = pk8;
                } else {
                    *(float2*)&g_v[bh2][s][d] = make_float2(v0, v1);
                    *(uint32_t*)&g_vh[bh2][s][d] = h2u(__floats2half2_rn(v0, v1));
                }
            }
        }
    }
}

// ==============================================================================
// fp16 GEMM (NT) for output projection, BM=128 BN=64 BK=32, 3-stage (round-12).
// A=g_yh, B=g_wph, row-major fp32 C + bias.
// ==============================================================================
#define P64_STAGE 15360
#define P64_SMEM  (3*P64_STAGE)

__global__ __launch_bounds__(256, 3) void proj64(
    const float* __restrict__ bias, float* __restrict__ C, int N, int K)
{
    extern __shared__ char smh[];
    const uint32_t smB = smem_u32(smh);

    const int tid  = threadIdx.x;
    const int warp = tid >> 5;
    const int lane = tid & 31;
    const int gr   = lane >> 2;
    const int tg   = lane & 3;
    const int wm   = (warp & 3) * 32;
    const int wn   = (warp >> 2) * 32;
    const int mb   = blockIdx.y * 128;
    const int nb   = blockIdx.x * 64;

    const int rowA = tid >> 1, cpA = (tid & 1) * 2;
    const int rowB = tid >> 2, chB = tid & 3;
    const __half* aHg = g_yh  + (size_t)(mb + rowA) * K + cpA * 8;
    const __half* bHg = g_wph + (size_t)(nb + rowB) * K + chB * 8;
    const uint32_t stA = rowA * 80 + cpA * 16;
    const uint32_t stB = 10240 + rowB * 80 + chB * 16;

    auto load_st = [&](int st, int k0) {
        const uint32_t d = smB + st * P64_STAGE;
        cp16(d + stA,      aHg + k0);
        cp16(d + stA + 16, aHg + k0 + 8);
        cp16(d + stB,      bHg + k0);
        asm volatile("cp.async.commit_group;\n");
    };

    float acc[2][4][4];
#pragma unroll
    for (int i = 0; i < 2; i++)
#pragma unroll
        for (int j = 0; j < 4; j++)
#pragma unroll
            for (int r = 0; r < 4; r++) acc[i][j][r] = 0.f;

    const uint32_t aOff = (wm + (lane & 15)) * 80 + (lane >> 4) * 16;
    const uint32_t bOff = 10240 + (wn + (lane & 15)) * 80 + (lane >> 4) * 16;

    const int nK = K / 32;
    load_st(0, 0);
    load_st(1, 32);

    for (int kt = 0; kt < nK; kt++) {
        asm volatile("cp.async.wait_group 1;\n");
        __syncthreads();
        if (kt + 2 < nK) load_st((kt + 2) % 3, (kt + 2) * 32);
        const uint32_t sb = smB + (kt % 3) * P64_STAGE;

#pragma unroll
        for (int s = 0; s < 2; s++) {
            uint32_t ah[2][4];
#pragma unroll
            for (int i = 0; i < 2; i++)
                ldsm4(ah[i][0], ah[i][1], ah[i][2], ah[i][3],
                      sb + aOff + i * 1280 + s * 32);
#pragma unroll
            for (int j = 0; j < 2; j++) {
                uint32_t bh_[4];
                ldsm4(bh_[0], bh_[1], bh_[2], bh_[3],
                      sb + bOff + j * 1280 + s * 32);
#pragma unroll
                for (int i = 0; i < 2; i++) {
                    mma_f16(acc[i][2*j  ], ah[i][0], ah[i][1], ah[i][2], ah[i][3], bh_[0], bh_[2]);
                    mma_f16(acc[i][2*j+1], ah[i][0], ah[i][1], ah[i][2], ah[i][3], bh_[1], bh_[3]);
                }
            }
        }
        __syncthreads();
    }

#pragma unroll
    for (int i = 0; i < 2; i++) {
#pragma unroll
        for (int j = 0; j < 4; j++) {
            const int r0 = mb + wm + i * 16 + gr;
            const int c0 = nb + wn + j * 8 + 2 * tg;
            const float bia0 = bias[c0], bia1 = bias[c0 + 1];
            float2 lo = make_float2(acc[i][j][0] + bia0, acc[i][j][1] + bia1);
            float2 hi = make_float2(acc[i][j][2] + bia0, acc[i][j][3] + bia1);
            *(float2*)&C[(size_t)r0 * N + c0]       = lo;
            *(float2*)&C[(size_t)(r0 + 8) * N + c0] = hi;
        }
    }
}

// ==============================================================================
// FUSED Laplacian (int8 SIMD distance) + attn@v + rownorm + depthwise conv.
// Grid (16 i-tiles of 64 rows, 32 bh), 256 threads / 8 warps.
// dist: vabsdiff4 (ALU pipe) + dp4a (FMA pipe) -> 0.5 inst/dim, dual-pipe.
// smem: qs 4352 | ks 2x4352 | kt 9216 | vh 2x9216 | rsum 256 = 40960 B
// ==============================================================================
#define QS_OFF   0
#define KS_OFF   4352
#define KT_OFF   13056
#define VH_OFF   22272
#define RS_OFF   40704
#define LAP_SMEM 40960

__global__ __launch_bounds__(256, 3) void lap_av(const float* __restrict__ dwc_w,
                                                 const float* __restrict__ dwc_b)
{
    extern __shared__ char sm[];
    const uint32_t smB = smem_u32(sm);

    const int tid  = threadIdx.x;
    const int tx   = tid & 15;
    const int ty   = tid >> 4;
    const int warp = tid >> 5;
    const int lane = tid & 31;
    const int gr   = lane >> 2;
    const int tg   = lane & 3;
    const int wm4  = (warp & 3) * 16;
    const int wn2  = (warp >> 2) * 32;
    const int it   = blockIdx.x;
    const int bh   = blockIdx.y;
    const int bb   = bh >> 4;
    const int h    = bh & 15;

    const char* Q8 = (const char*)&g_qk8[0][bh][0][0];
    const char* K8 = (const char*)&g_qk8[1][bh][0][0];
    const __half* Vh = &g_vh[bh][0][0];
    const float*  V  = &g_v[bh][0][0];

    const int d4s = tid >> 4, cs = tid & 15;   // q/k staging coords (1 chunk/thr)

    auto stage_q = [&]() {
        cp16(smB + QS_OFF + d4s * 272 + cs * 16,
             Q8 + (size_t)d4s * 4096 + (size_t)it * 256 + cs * 16);
    };
    auto stage_k = [&](int buf, int jt) {
        cp16(smB + KS_OFF + buf * 4352 + d4s * 272 + cs * 16,
             K8 + (size_t)d4s * 4096 + (size_t)jt * 256 + cs * 16);
    };
    auto stage_v = [&](int buf, int jt) {
#pragma unroll
        for (int r = 0; r < 2; r++) {
            int idx = tid + r * 256;
            int j = idx >> 3, c = idx & 7;
            cp16(smB + VH_OFF + buf * 9216 + j * 144 + c * 16,
                 (const char*)Vh + ((size_t)(jt * 64 + j) * 64 + c * 8) * 2);
        }
    };

    const uint32_t aKt = smB + KT_OFF
        + (wm4 + (lane & 7) + ((lane >> 3) & 1) * 8) * 144 + (lane >> 4) * 16;
    const uint32_t bVh = smB + VH_OFF
        + (lane & 15) * 144 + (lane >> 4) * 16 + wn2 * 2;

    stage_q(); stage_k(0, 0); stage_v(0, 0);
    asm volatile("cp.async.commit_group;\n");

    float rs[4] = {0.f, 0.f, 0.f, 0.f};
    float macc[4][4];
#pragma unroll
    for (int n = 0; n < 4; n++)
#pragma unroll
        for (int e = 0; e < 4; e++) macc[n][e] = 0.f;

    const uint32_t* qsP = (const uint32_t*)(sm + QS_OFF);

    for (int jt = 0; jt < 16; jt++) {
        const int buf = jt & 1;
        asm volatile("cp.async.wait_group 0;\n");
        __syncthreads();
        if (jt < 15) {
            stage_k(buf ^ 1, jt + 1);
            stage_v(buf ^ 1, jt + 1);
            asm volatile("cp.async.commit_group;\n");
        }

        // ---- dist phase: int8 SIMD (vabsdiff4 + dp4a) ----
        const uint32_t* ksP = (const uint32_t*)(sm + KS_OFF + buf * 4352);
        unsigned acc[4][4];
#pragma unroll
        for (int ii = 0; ii < 4; ii++)
#pragma unroll
            for (int jj = 0; jj < 4; jj++) acc[ii][jj] = 0u;

#pragma unroll
        for (int d4 = 0; d4 < 16; d4++) {
            uint4 qv = *(const uint4*)(qsP + d4 * 68 + ty * 4);
            uint4 kv = *(const uint4*)(ksP + d4 * 68 + tx * 4);
            uint32_t q2[4] = {qv.x, qv.y, qv.z, qv.w};
            uint32_t k2[4] = {kv.x, kv.y, kv.z, kv.w};
#pragma unroll
            for (int ii = 0; ii < 4; ii++)
#pragma unroll
                for (int jj = 0; jj < 4; jj++)
                    acc[ii][jj] = __dp4a(__vabsdiffs4(q2[ii], k2[jj]),
                                         0x01010101u, acc[ii][jj]);
        }

#pragma unroll
        for (int ii = 0; ii < 4; ii++) {
            float op[4];
#pragma unroll
            for (int jj = 0; jj < 4; jj++) {
                float kvf = __expf(KERN_COEF * (float)acc[ii][jj]);
                op[jj] = kvf;
                rs[ii] += kvf;
            }
            *(uint2*)(sm + KT_OFF + (ty*4 + ii) * 144 + tx * 8)
                = make_uint2(h2u(__floats2half2_rn(op[0], op[1])),
                             h2u(__floats2half2_rn(op[2], op[3])));
        }
        __syncthreads();

        // ---- mma phase: macc += kt @ vh[buf] ----
        const uint32_t bB = bVh + buf * 9216;
#pragma unroll
        for (int k16 = 0; k16 < 4; k16++) {
            uint32_t a0, a1, a2, a3;
            ldsm4(a0, a1, a2, a3, aKt + k16 * 32);
#pragma unroll
            for (int nf2 = 0; nf2 < 2; nf2++) {
                uint32_t b0, b1, b2, b3;
                ldsm4t(b0, b1, b2, b3, bB + k16 * 2304 + nf2 * 32);
                mma_f16(macc[2*nf2    ], a0, a1, a2, a3, b0, b1);
                mma_f16(macc[2*nf2 + 1], a0, a1, a2, a3, b2, b3);
            }
        }
    }

    float* rsum = (float*)(sm + RS_OFF);
#pragma unroll
    for (int ii = 0; ii < 4; ii++) {
        float v = rs[ii];
        v += __shfl_xor_sync(0xffffffffu, v, 1);
        v += __shfl_xor_sync(0xffffffffu, v, 2);
        v += __shfl_xor_sync(0xffffffffu, v, 4);
        v += __shfl_xor_sync(0xffffffffu, v, 8);
        if (tx == 0) rsum[ty*4 + ii] = v;
    }
    __syncthreads();

#pragma unroll
    for (int nf = 0; nf < 4; nf++) {
        const int dl = wn2 + nf * 8 + tg * 2;
        const int c  = h * 64 + dl;
        const float w0a = dwc_w[c*3+0], w1a = dwc_w[c*3+1], w2a = dwc_w[c*3+2];
        const float b0a = dwc_b[c];
        const float w0b = dwc_w[c*3+3], w1b = dwc_w[c*3+4], w2b = dwc_w[c*3+5];
        const float b1b = dwc_b[c+1];
#pragma unroll
        for (int half = 0; half < 2; half++) {
            const int il = wm4 + gr + half * 8;
            const int s  = it * 64 + il;
            const float sc = 1.0f / (rsum[il] + 1e-6f);
            float o0 = macc[nf][half*2 + 0] * sc;
            float o1 = macc[nf][half*2 + 1] * sc;
            float2 v0 = *(const float2*)&V[(size_t)s*64 + dl];
            float2 vm = (s > 0)       ? *(const float2*)&V[(size_t)(s-1)*64 + dl]
                                      : make_float2(0.f, 0.f);
            float2 vp = (s < SEQ - 1) ? *(const float2*)&V[(size_t)(s+1)*64 + dl]
                                      : make_float2(0.f, 0.f);
            o0 += w0a*vm.x + w1a*v0.x + w2a*vp.x + b0a;
            o1 += w0b*vm.y + w1b*v0.y + w2b*vp.y + b1b;
            const size_t oidx = (size_t)(bb*SEQ + s) * 1024 + c;
            *(uint32_t*)&g_yh[oidx] = h2u(__floats2half2_rn(o0, o1));
        }
    }
}

// ==============================================================================
extern "C" void kernel_launch(void* const* d_in, const int* in_sizes, int n_in,
                              void* d_out, int out_size)
{
    const float* x      = (const float*)d_in[0];
    const float* qkv_w  = (const float*)d_in[1];
    const float* qkv_b  = (const float*)d_in[2];
    const float* proj_w = (const float*)d_in[3];
    const float* proj_b = (const float*)d_in[4];
    const float* dwc_w  = (const float*)d_in[5];
    const float* dwc_b  = (const float*)d_in[6];
    float* out = (float*)d_out;

    cudaFuncSetAttribute(hgemm_qkv, cudaFuncAttributeMaxDynamicSharedMemorySize, HG_SMEM);
    cudaFuncSetAttribute(proj64,    cudaFuncAttributeMaxDynamicSharedMemorySize, P64_SMEM);
    cudaFuncSetAttribute(lap_av,    cudaFuncAttributeMaxDynamicSharedMemorySize, LAP_SMEM);

    // 0) convert x / weights to fp16 scratch
    prep_f16<<<dim3(3072, 3), 256>>>(x, qkv_w, proj_w);
    // 1) qkv projection (fp16 HMMA); q,k -> int8 packed, v -> fp32+fp16
    hgemm_qkv<<<dim3(24, 16), 256, HG_SMEM>>>(qkv_b, 3072, 1024);
    // 2) FUSED Laplacian (int8 SIMD dist) + attn@v + rownorm + dwc -> y (fp16)
    lap_av<<<dim3(16, 32), 256, LAP_SMEM>>>(dwc_w, dwc_b);
    // 3) output projection (fp16 HMMA, BN=64, 3-stage) -> d_out
    proj64<<<dim3(16, 16), 256, P64_SMEM>>>(proj_b, out, 1024, 1024);
}

// round 15
// speedup vs baseline: 1.5290x; 1.0248x over previous
#include <cuda_runtime.h>
#include <cuda_fp16.h>
#include <cstdint>

#define SEQ 1024
#define DIMC 1024
#define NHEADS 16
#define HDIM 64
#define NBATCH 2
#define NBH (NBATCH*NHEADS)   // 32

// ---------------- scratch (device globals; no runtime allocation) -------------
__device__ float    g_v[NBH][SEQ][HDIM];        // 8 MB  v fp32 (dwc epilogue)
__device__ __half   g_vh[NBH][SEQ][HDIM];       // 4 MB  v fp16 (mma operand)
__device__ uint32_t g_qk8[2][NBH][16][1024];    // 4 MB  q,k int8x4: [d4][s]
__device__ __half   g_xh[2048*1024];            // fp16 x
__device__ __half   g_wqh[3072*1024];           // fp16 qkv_w
__device__ __half   g_wph[1024*1024];           // fp16 proj_w
__device__ __half   g_yh[2048*1024];            // fp16 pre-projection activations

#define QSCALE  32.0f
// ex2 coefficient: -LAMBDA/HEAD_DIM/QSCALE * log2(e) = -0.0625/32 * 1.4426950
#define C2F     (-2.8177637e-3f)

// ---------------- helpers ------------------------------------------------------
__device__ __forceinline__ uint32_t smem_u32(const void* p) {
    return (uint32_t)__cvta_generic_to_shared(p);
}
__device__ __forceinline__ void cp16(uint32_t s, const void* g) {
    asm volatile("cp.async.cg.shared.global [%0], [%1], 16;\n" :: "r"(s), "l"(g));
}
__device__ __forceinline__ void mma_f16(float c[4],
        uint32_t a0, uint32_t a1, uint32_t a2, uint32_t a3,
        uint32_t b0, uint32_t b1) {
    asm volatile(
        "mma.sync.aligned.m16n8k16.row.col.f32.f16.f16.f32 "
        "{%0,%1,%2,%3}, {%4,%5,%6,%7}, {%8,%9}, {%0,%1,%2,%3};"
        : "+f"(c[0]), "+f"(c[1]), "+f"(c[2]), "+f"(c[3])
        : "r"(a0), "r"(a1), "r"(a2), "r"(a3), "r"(b0), "r"(b1));
}
__device__ __forceinline__ void ldsm4(uint32_t& r0, uint32_t& r1,
                                      uint32_t& r2, uint32_t& r3, uint32_t a) {
    asm volatile("ldmatrix.sync.aligned.m8n8.x4.shared.b16 {%0,%1,%2,%3}, [%4];"
                 : "=r"(r0), "=r"(r1), "=r"(r2), "=r"(r3) : "r"(a));
}
__device__ __forceinline__ void ldsm4t(uint32_t& r0, uint32_t& r1,
                                       uint32_t& r2, uint32_t& r3, uint32_t a) {
    asm volatile("ldmatrix.sync.aligned.m8n8.x4.trans.shared.b16 {%0,%1,%2,%3}, [%4];"
                 : "=r"(r0), "=r"(r1), "=r"(r2), "=r"(r3) : "r"(a));
}
__device__ __forceinline__ uint32_t h2u(__half2 h) { return *(uint32_t*)&h; }
__device__ __forceinline__ __half2 u2h(uint32_t u) { return *(__half2*)&u; }
// pack two f32 into f16x2 (lo = a0, hi = a1), then 2^x on both halves
__device__ __forceinline__ uint32_t ex2_h2(float a0, float a1) {
    uint32_t p, r;
    asm("cvt.rn.f16x2.f32 %0, %1, %2;" : "=r"(p) : "f"(a1), "f"(a0));
    asm("ex2.approx.f16x2 %0, %1;" : "=r"(r) : "r"(p));
    return r;
}

// ==============================================================================
// Prepass: convert x / qkv_w / proj_w to fp16 scratch copies.
// ==============================================================================
__global__ __launch_bounds__(256) void prep_f16(const float* __restrict__ x,
                                                const float* __restrict__ wq,
                                                const float* __restrict__ wp)
{
    const float4* src; __half* dh; int n4;
    if (blockIdx.y == 0)      { src = (const float4*)x;  dh = g_xh;  n4 = 524288; }
    else if (blockIdx.y == 1) { src = (const float4*)wq; dh = g_wqh; n4 = 786432; }
    else                      { src = (const float4*)wp; dh = g_wph; n4 = 262144; }
    int i = blockIdx.x * 256 + threadIdx.x;
    if (i < n4) {
        float4 v = src[i];
        ((uint2*)dh)[i] = make_uint2(h2u(__floats2half2_rn(v.x, v.y)),
                                     h2u(__floats2half2_rn(v.z, v.w)));
    }
}

// ==============================================================================
// fp16 tensor-core GEMM (NT), BM=128 BN=128 BK=32, 2-stage (proven).
// A=x, B=qkv_w; q,k -> g_qk8 (int8 packed, QSCALE), v -> g_v + g_vh.
// ==============================================================================
#define HG_STAGE 20480
#define HG_SMEM  (2*HG_STAGE)

__global__ __launch_bounds__(256, 2) void hgemm_qkv(
    const float* __restrict__ bias, int N, int K)
{
    extern __shared__ char smh[];
    const uint32_t smB = smem_u32(smh);

    const int tid  = threadIdx.x;
    const int warp = tid >> 5;
    const int lane = tid & 31;
    const int gr   = lane >> 2;
    const int tg   = lane & 3;
    const int wm   = (warp & 3) * 32;
    const int wn   = (warp >> 2) * 64;
    const int mb   = blockIdx.y * 128;
    const int nb   = blockIdx.x * 128;

    const int row = tid >> 1;
    const int cp  = (tid & 1) * 2;
    const __half* aHg = g_xh  + (size_t)(mb + row) * K + cp * 8;
    const __half* bHg = g_wqh + (size_t)(nb + row) * K + cp * 8;
    const uint32_t stDst = row * 80 + cp * 16;

    auto load_st = [&](int st, int k0) {
        const uint32_t d = smB + st * HG_STAGE + stDst;
        cp16(d,         aHg + k0); cp16(d + 16,         aHg + k0 + 8);
        cp16(d + 10240, bHg + k0); cp16(d + 10240 + 16, bHg + k0 + 8);
        asm volatile("cp.async.commit_group;\n");
    };

    float acc[2][8][4];
#pragma unroll
    for (int i = 0; i < 2; i++)
#pragma unroll
        for (int j = 0; j < 8; j++)
#pragma unroll
            for (int r = 0; r < 4; r++) acc[i][j][r] = 0.f;

    const uint32_t aOff = (wm + (lane & 15)) * 80 + (lane >> 4) * 16;
    const uint32_t bOff = (wn + (lane & 15)) * 80 + (lane >> 4) * 16 + 10240;

    const int nK = K / 32;
    load_st(0, 0);

    for (int kt = 0; kt < nK; kt++) {
        asm volatile("cp.async.wait_group 0;\n");
        __syncthreads();
        if (kt + 1 < nK) load_st((kt + 1) & 1, (kt + 1) * 32);
        const uint32_t sb = smB + (kt & 1) * HG_STAGE;

#pragma unroll
        for (int s = 0; s < 2; s++) {
            uint32_t ah[2][4];
#pragma unroll
            for (int i = 0; i < 2; i++)
                ldsm4(ah[i][0], ah[i][1], ah[i][2], ah[i][3],
                      sb + aOff + i * 1280 + s * 32);
#pragma unroll
            for (int j = 0; j < 4; j++) {
                uint32_t bh_[4];
                ldsm4(bh_[0], bh_[1], bh_[2], bh_[3],
                      sb + bOff + j * 1280 + s * 32);
#pragma unroll
                for (int i = 0; i < 2; i++) {
                    mma_f16(acc[i][2*j  ], ah[i][0], ah[i][1], ah[i][2], ah[i][3], bh_[0], bh_[2]);
                    mma_f16(acc[i][2*j+1], ah[i][0], ah[i][1], ah[i][2], ah[i][3], bh_[1], bh_[3]);
                }
            }
        }
    }

#pragma unroll
    for (int i = 0; i < 2; i++) {
#pragma unroll
        for (int j = 0; j < 8; j++) {
            const int r0 = mb + wm + i * 16 + gr;
            const int c0 = nb + wn + j * 8 + 2 * tg;     // even
            const float bia0 = bias[c0], bia1 = bias[c0 + 1];
            const int tsel = c0 >> 10, rem = c0 & 1023;
            const int hh = rem >> 6, d = rem & 63;
#pragma unroll
            for (int pr = 0; pr < 2; pr++) {
                const int m = r0 + pr * 8;
                const int bb = m >> 10, s = m & 1023;
                const int bh2 = bb * NHEADS + hh;
                const float v0 = acc[i][j][pr*2 + 0] + bia0;
                const float v1 = acc[i][j][pr*2 + 1] + bia1;
                if (tsel < 2) {
                    int i0 = __float2int_rn(fminf(fmaxf(v0 * QSCALE, -127.f), 127.f));
                    int i1 = __float2int_rn(fminf(fmaxf(v1 * QSCALE, -127.f), 127.f));
                    unsigned short pk8 = (unsigned short)((i0 & 0xFF) | ((i1 & 0xFF) << 8));
                    *(unsigned short*)((char*)&g_qk8[tsel][bh2][d >> 2][s] + (d & 3)) = pk8;
                } else {
                    *(float2*)&g_v[bh2][s][d] = make_float2(v0, v1);
                    *(uint32_t*)&g_vh[bh2][s][d] = h2u(__floats2half2_rn(v0, v1));
                }
            }
        }
    }
}

// ==============================================================================
// fp16 GEMM (NT) for output projection, BM=128 BN=64 BK=32, 3-stage (proven).
// ==============================================================================
#define P64_STAGE 15360
#define P64_SMEM  (3*P64_STAGE)

__global__ __launch_bounds__(256, 3) void proj64(
    const float* __restrict__ bias, float* __restrict__ C, int N, int K)
{
    extern __shared__ char smh[];
    const uint32_t smB = smem_u32(smh);

    const int tid  = threadIdx.x;
    const int warp = tid >> 5;
    const int lane = tid & 31;
    const int gr   = lane >> 2;
    const int tg   = lane & 3;
    const int wm   = (warp & 3) * 32;
    const int wn   = (warp >> 2) * 32;
    const int mb   = blockIdx.y * 128;
    const int nb   = blockIdx.x * 64;

    const int rowA = tid >> 1, cpA = (tid & 1) * 2;
    const int rowB = tid >> 2, chB = tid & 3;
    const __half* aHg = g_yh  + (size_t)(mb + rowA) * K + cpA * 8;
    const __half* bHg = g_wph + (size_t)(nb + rowB) * K + chB * 8;
    const uint32_t stA = rowA * 80 + cpA * 16;
    const uint32_t stB = 10240 + rowB * 80 + chB * 16;

    auto load_st = [&](int st, int k0) {
        const uint32_t d = smB + st * P64_STAGE;
        cp16(d + stA,      aHg + k0);
        cp16(d + stA + 16, aHg + k0 + 8);
        cp16(d + stB,      bHg + k0);
        asm volatile("cp.async.commit_group;\n");
    };

    float acc[2][4][4];
#pragma unroll
    for (int i = 0; i < 2; i++)
#pragma unroll
        for (int j = 0; j < 4; j++)
#pragma unroll
            for (int r = 0; r < 4; r++) acc[i][j][r] = 0.f;

    const uint32_t aOff = (wm + (lane & 15)) * 80 + (lane >> 4) * 16;
    const uint32_t bOff = 10240 + (wn + (lane & 15)) * 80 + (lane >> 4) * 16;

    const int nK = K / 32;
    load_st(0, 0);
    load_st(1, 32);

    for (int kt = 0; kt < nK; kt++) {
        asm volatile("cp.async.wait_group 1;\n");
        __syncthreads();
        if (kt + 2 < nK) load_st((kt + 2) % 3, (kt + 2) * 32);
        const uint32_t sb = smB + (kt % 3) * P64_STAGE;

#pragma unroll
        for (int s = 0; s < 2; s++) {
            uint32_t ah[2][4];
#pragma unroll
            for (int i = 0; i < 2; i++)
                ldsm4(ah[i][0], ah[i][1], ah[i][2], ah[i][3],
                      sb + aOff + i * 1280 + s * 32);
#pragma unroll
            for (int j = 0; j < 2; j++) {
                uint32_t bh_[4];
                ldsm4(bh_[0], bh_[1], bh_[2], bh_[3],
                      sb + bOff + j * 1280 + s * 32);
#pragma unroll
                for (int i = 0; i < 2; i++) {
                    mma_f16(acc[i][2*j  ], ah[i][0], ah[i][1], ah[i][2], ah[i][3], bh_[0], bh_[2]);
                    mma_f16(acc[i][2*j+1], ah[i][0], ah[i][1], ah[i][2], ah[i][3], bh_[1], bh_[3]);
                }
            }
        }
        __syncthreads();
    }

#pragma unroll
    for (int i = 0; i < 2; i++) {
#pragma unroll
        for (int j = 0; j < 4; j++) {
            const int r0 = mb + wm + i * 16 + gr;
            const int c0 = nb + wn + j * 8 + 2 * tg;
            const float bia0 = bias[c0], bia1 = bias[c0 + 1];
            float2 lo = make_float2(acc[i][j][0] + bia0, acc[i][j][1] + bia1);
            float2 hi = make_float2(acc[i][j][2] + bia0, acc[i][j][3] + bia1);
            *(float2*)&C[(size_t)r0 * N + c0]       = lo;
            *(float2*)&C[(size_t)(r0 + 8) * N + c0] = hi;
        }
    }
}

// ==============================================================================
// FUSED Laplacian (int8 SIMD dist + ex2.f16x2) + attn@v + rownorm + dwc.
// Grid (16 i-tiles of 64 rows, 32 bh), 256 threads / 8 warps.
// dist: vabsdiff4 (ALU) + dp4a (FMA); kern: ex2.approx.f16x2 (MUFU halved).
// smem: qs 4352 | ks 2x4352 | kt 9216 | vh 2x9216 | rsum 256 = 40960 B
// ==============================================================================
#define QS_OFF   0
#define KS_OFF   4352
#define KT_OFF   13056
#define VH_OFF   22272
#define RS_OFF   40704
#define LAP_SMEM 40960

__global__ __launch_bounds__(256, 3) void lap_av(const float* __restrict__ dwc_w,
                                                 const float* __restrict__ dwc_b)
{
    extern __shared__ char sm[];
    const uint32_t smB = smem_u32(sm);

    const int tid  = threadIdx.x;
    const int tx   = tid & 15;
    const int ty   = tid >> 4;
    const int warp = tid >> 5;
    const int lane = tid & 31;
    const int gr   = lane >> 2;
    const int tg   = lane & 3;
    const int wm4  = (warp & 3) * 16;
    const int wn2  = (warp >> 2) * 32;
    const int it   = blockIdx.x;
    const int bh   = blockIdx.y;
    const int bb   = bh >> 4;
    const int h    = bh & 15;

    const char* Q8 = (const char*)&g_qk8[0][bh][0][0];
    const char* K8 = (const char*)&g_qk8[1][bh][0][0];
    const __half* Vh = &g_vh[bh][0][0];
    const float*  V  = &g_v[bh][0][0];

    const int d4s = tid >> 4, cs = tid & 15;

    auto stage_q = [&]() {
        cp16(smB + QS_OFF + d4s * 272 + cs * 16,
             Q8 + (size_t)d4s * 4096 + (size_t)it * 256 + cs * 16);
    };
    auto stage_k = [&](int buf, int jt) {
        cp16(smB + KS_OFF + buf * 4352 + d4s * 272 + cs * 16,
             K8 + (size_t)d4s * 4096 + (size_t)jt * 256 + cs * 16);
    };
    auto stage_v = [&](int buf, int jt) {
#pragma unroll
        for (int r = 0; r < 2; r++) {
            int idx = tid + r * 256;
            int j = idx >> 3, c = idx & 7;
            cp16(smB + VH_OFF + buf * 9216 + j * 144 + c * 16,
                 (const char*)Vh + ((size_t)(jt * 64 + j) * 64 + c * 8) * 2);
        }
    };

    const uint32_t aKt = smB + KT_OFF
        + (wm4 + (lane & 7) + ((lane >> 3) & 1) * 8) * 144 + (lane >> 4) * 16;
    const uint32_t bVh = smB + VH_OFF
        + (lane & 15) * 144 + (lane >> 4) * 16 + wn2 * 2;

    stage_q(); stage_k(0, 0); stage_v(0, 0);
    asm volatile("cp.async.commit_group;\n");

    float rs[4] = {0.f, 0.f, 0.f, 0.f};
    float macc[4][4];
#pragma unroll
    for (int n = 0; n < 4; n++)
#pragma unroll
        for (int e = 0; e < 4; e++) macc[n][e] = 0.f;

    const uint32_t* qsP = (const uint32_t*)(sm + QS_OFF);

    for (int jt = 0; jt < 16; jt++) {
        const int buf = jt & 1;
        asm volatile("cp.async.wait_group 0;\n");
        __syncthreads();
        if (jt < 15) {
            stage_k(buf ^ 1, jt + 1);
            stage_v(buf ^ 1, jt + 1);
            asm volatile("cp.async.commit_group;\n");
        }

        // ---- dist phase: int8 SIMD (vabsdiff4 + dp4a) ----
        const uint32_t* ksP = (const uint32_t*)(sm + KS_OFF + buf * 4352);
        unsigned acc[4][4];
#pragma unroll
        for (int ii = 0; ii < 4; ii++)
#pragma unroll
            for (int jj = 0; jj < 4; jj++) acc[ii][jj] = 0u;

#pragma unroll
        for (int d4 = 0; d4 < 16; d4++) {
            uint4 qv = *(const uint4*)(qsP + d4 * 68 + ty * 4);
            uint4 kv = *(const uint4*)(ksP + d4 * 68 + tx * 4);
            uint32_t q2[4] = {qv.x, qv.y, qv.z, qv.w};
            uint32_t k2[4] = {kv.x, kv.y, kv.z, kv.w};
#pragma unroll
            for (int ii = 0; ii < 4; ii++)
#pragma unroll
                for (int jj = 0; jj < 4; jj++)
                    acc[ii][jj] = __dp4a(__vabsdiffs4(q2[ii], k2[jj]),
                                         0x01010101u, acc[ii][jj]);
        }

        // ---- kern tile: ex2.approx.f16x2 (fp16 out, rowsum from same values) --
#pragma unroll
        for (int ii = 0; ii < 4; ii++) {
            float a0 = (float)acc[ii][0] * C2F;
            float a1 = (float)acc[ii][1] * C2F;
            float a2 = (float)acc[ii][2] * C2F;
            float a3 = (float)acc[ii][3] * C2F;
            uint32_t k01 = ex2_h2(a0, a1);
            uint32_t k23 = ex2_h2(a2, a3);
            *(uint2*)(sm + KT_OFF + (ty*4 + ii) * 144 + tx * 8)
                = make_uint2(k01, k23);
            float2 fr = __half22float2(__hadd2(u2h(k01), u2h(k23)));
            rs[ii] += fr.x + fr.y;
        }
        __syncthreads();

        // ---- mma phase: macc += kt @ vh[buf] ----
        const uint32_t bB = bVh + buf * 9216;
#pragma unroll
        for (int k16 = 0; k16 < 4; k16++) {
            uint32_t a0, a1, a2, a3;
            ldsm4(a0, a1, a2, a3, aKt + k16 * 32);
#pragma unroll
            for (int nf2 = 0; nf2 < 2; nf2++) {
                uint32_t b0, b1, b2, b3;
                ldsm4t(b0, b1, b2, b3, bB + k16 * 2304 + nf2 * 32);
                mma_f16(macc[2*nf2    ], a0, a1, a2, a3, b0, b1);
                mma_f16(macc[2*nf2 + 1], a0, a1, a2, a3, b2, b3);
            }
        }
    }

    float* rsum = (float*)(sm + RS_OFF);
#pragma unroll
    for (int ii = 0; ii < 4; ii++) {
        float v = rs[ii];
        v += __shfl_xor_sync(0xffffffffu, v, 1);
        v += __shfl_xor_sync(0xffffffffu, v, 2);
        v += __shfl_xor_sync(0xffffffffu, v, 4);
        v += __shfl_xor_sync(0xffffffffu, v, 8);
        if (tx == 0) rsum[ty*4 + ii] = v;
    }
    __syncthreads();

#pragma unroll
    for (int nf = 0; nf < 4; nf++) {
        const int dl = wn2 + nf * 8 + tg * 2;
        const int c  = h * 64 + dl;
        const float w0a = dwc_w[c*3+0], w1a = dwc_w[c*3+1], w2a = dwc_w[c*3+2];
        const float b0a = dwc_b[c];
        const float w0b = dwc_w[c*3+3], w1b = dwc_w[c*3+4], w2b = dwc_w[c*3+5];
        const float b1b = dwc_b[c+1];
#pragma unroll
        for (int half = 0; half < 2; half++) {
            const int il = wm4 + gr + half * 8;
            const int s  = it * 64 + il;
            const float sc = 1.0f / (rsum[il] + 1e-6f);
            float o0 = macc[nf][half*2 + 0] * sc;
            float o1 = macc[nf][half*2 + 1] * sc;
            float2 v0 = *(const float2*)&V[(size_t)s*64 + dl];
            float2 vm = (s > 0)       ? *(const float2*)&V[(size_t)(s-1)*64 + dl]
                                      : make_float2(0.f, 0.f);
            float2 vp = (s < SEQ - 1) ? *(const float2*)&V[(size_t)(s+1)*64 + dl]
                                      : make_float2(0.f, 0.f);
            o0 += w0a*vm.x + w1a*v0.x + w2a*vp.x + b0a;
            o1 += w0b*vm.y + w1b*v0.y + w2b*vp.y + b1b;
            const size_t oidx = (size_t)(bb*SEQ + s) * 1024 + c;
            *(uint32_t*)&g_yh[oidx] = h2u(__floats2half2_rn(o0, o1));
        }
    }
}

// ==============================================================================
extern "C" void kernel_launch(void* const* d_in, const int* in_sizes, int n_in,
                              void* d_out, int out_size)
{
    const float* x      = (const float*)d_in[0];
    const float* qkv_w  = (const float*)d_in[1];
    const float* qkv_b  = (const float*)d_in[2];
    const float* proj_w = (const float*)d_in[3];
    const float* proj_b = (const float*)d_in[4];
    const float* dwc_w  = (const float*)d_in[5];
    const float* dwc_b  = (const float*)d_in[6];
    float* out = (float*)d_out;

    cudaFuncSetAttribute(hgemm_qkv, cudaFuncAttributeMaxDynamicSharedMemorySize, HG_SMEM);
    cudaFuncSetAttribute(proj64,    cudaFuncAttributeMaxDynamicSharedMemorySize, P64_SMEM);
    cudaFuncSetAttribute(lap_av,    cudaFuncAttributeMaxDynamicSharedMemorySize, LAP_SMEM);

    // 0) convert x / weights to fp16 scratch
    prep_f16<<<dim3(3072, 3), 256>>>(x, qkv_w, proj_w);
    // 1) qkv projection (fp16 HMMA); q,k -> int8 packed, v -> fp32+fp16
    hgemm_qkv<<<dim3(24, 16), 256, HG_SMEM>>>(qkv_b, 3072, 1024);
    // 2) FUSED Laplacian (int8 dist + ex2.f16x2) + attn@v + rownorm + dwc -> y
    lap_av<<<dim3(16, 32), 256, LAP_SMEM>>>(dwc_w, dwc_b);
    // 3) output projection (fp16 HMMA, BN=64, 3-stage) -> d_out
    proj64<<<dim3(16, 16), 256, P64_SMEM>>>(proj_b, out, 1024, 1024);
}

// round 16
// speedup vs baseline: 1.5437x; 1.0096x over previous
#include <cuda_runtime.h>
#include <cuda_fp16.h>
#include <cstdint>

#define SEQ 1024
#define DIMC 1024
#define NHEADS 16
#define HDIM 64
#define NBATCH 2
#define NBH (NBATCH*NHEADS)   // 32

// ---------------- scratch (device globals; no runtime allocation) -------------
__device__ __half   g_vh[NBH][SEQ][HDIM];       // 4 MB  v fp16 (mma + dwc)
__device__ uint32_t g_qk8[2][NBH][16][1024];    // 4 MB  q,k int8x4: [d4][s]
__device__ __half   g_xh[2048*1024];            // fp16 x
__device__ __half   g_wqh[3072*1024];           // fp16 qkv_w
__device__ __half   g_wph[1024*1024];           // fp16 proj_w
__device__ __half   g_yh[2048*1024];            // fp16 pre-projection activations

#define QSCALE  32.0f
// ex2 coefficient: -LAMBDA/HEAD_DIM/QSCALE * log2(e) = -0.0625/32 * 1.4426950
#define C2F     (-2.8177637e-3f)

// ---------------- helpers ------------------------------------------------------
__device__ __forceinline__ uint32_t smem_u32(const void* p) {
    return (uint32_t)__cvta_generic_to_shared(p);
}
__device__ __forceinline__ void cp16(uint32_t s, const void* g) {
    asm volatile("cp.async.cg.shared.global [%0], [%1], 16;\n" :: "r"(s), "l"(g));
}
__device__ __forceinline__ void mma_f16(float c[4],
        uint32_t a0, uint32_t a1, uint32_t a2, uint32_t a3,
        uint32_t b0, uint32_t b1) {
    asm volatile(
        "mma.sync.aligned.m16n8k16.row.col.f32.f16.f16.f32 "
        "{%0,%1,%2,%3}, {%4,%5,%6,%7}, {%8,%9}, {%0,%1,%2,%3};"
        : "+f"(c[0]), "+f"(c[1]), "+f"(c[2]), "+f"(c[3])
        : "r"(a0), "r"(a1), "r"(a2), "r"(a3), "r"(b0), "r"(b1));
}
__device__ __forceinline__ void ldsm4(uint32_t& r0, uint32_t& r1,
                                      uint32_t& r2, uint32_t& r3, uint32_t a) {
    asm volatile("ldmatrix.sync.aligned.m8n8.x4.shared.b16 {%0,%1,%2,%3}, [%4];"
                 : "=r"(r0), "=r"(r1), "=r"(r2), "=r"(r3) : "r"(a));
}
__device__ __forceinline__ void ldsm4t(uint32_t& r0, uint32_t& r1,
                                       uint32_t& r2, uint32_t& r3, uint32_t a) {
    asm volatile("ldmatrix.sync.aligned.m8n8.x4.trans.shared.b16 {%0,%1,%2,%3}, [%4];"
                 : "=r"(r0), "=r"(r1), "=r"(r2), "=r"(r3) : "r"(a));
}
__device__ __forceinline__ uint32_t h2u(__half2 h) { return *(uint32_t*)&h; }
__device__ __forceinline__ __half2 u2h(uint32_t u) { return *(__half2*)&u; }
// pack two f32 into f16x2 (lo = a0, hi = a1), then 2^x on both halves
__device__ __forceinline__ uint32_t ex2_h2(float a0, float a1) {
    uint32_t p, r;
    asm("cvt.rn.f16x2.f32 %0, %1, %2;" : "=r"(p) : "f"(a1), "f"(a0));
    asm("ex2.approx.f16x2 %0, %1;" : "=r"(r) : "r"(p));
    return r;
}

// ==============================================================================
// Prepass: convert x / qkv_w / proj_w to fp16 scratch copies.
// ==============================================================================
__global__ __launch_bounds__(256) void prep_f16(const float* __restrict__ x,
                                                const float* __restrict__ wq,
                                                const float* __restrict__ wp)
{
    const float4* src; __half* dh; int n4;
    if (blockIdx.y == 0)      { src = (const float4*)x;  dh = g_xh;  n4 = 524288; }
    else if (blockIdx.y == 1) { src = (const float4*)wq; dh = g_wqh; n4 = 786432; }
    else                      { src = (const float4*)wp; dh = g_wph; n4 = 262144; }
    int i = blockIdx.x * 256 + threadIdx.x;
    if (i < n4) {
        float4 v = src[i];
        ((uint2*)dh)[i] = make_uint2(h2u(__floats2half2_rn(v.x, v.y)),
                                     h2u(__floats2half2_rn(v.z, v.w)));
    }
}

// ==============================================================================
// fp16 tensor-core GEMM (NT), BM=128 BN=128 BK=32, 2-stage (proven).
// A=x, B=qkv_w; q,k -> g_qk8 (int8 packed, QSCALE), v -> g_vh (fp16 only).
// ==============================================================================
#define HG_STAGE 20480
#define HG_SMEM  (2*HG_STAGE)

__global__ __launch_bounds__(256, 2) void hgemm_qkv(
    const float* __restrict__ bias, int N, int K)
{
    extern __shared__ char smh[];
    const uint32_t smB = smem_u32(smh);

    const int tid  = threadIdx.x;
    const int warp = tid >> 5;
    const int lane = tid & 31;
    const int gr   = lane >> 2;
    const int tg   = lane & 3;
    const int wm   = (warp & 3) * 32;
    const int wn   = (warp >> 2) * 64;
    const int mb   = blockIdx.y * 128;
    const int nb   = blockIdx.x * 128;

    const int row = tid >> 1;
    const int cp  = (tid & 1) * 2;
    const __half* aHg = g_xh  + (size_t)(mb + row) * K + cp * 8;
    const __half* bHg = g_wqh + (size_t)(nb + row) * K + cp * 8;
    const uint32_t stDst = row * 80 + cp * 16;

    auto load_st = [&](int st, int k0) {
        const uint32_t d = smB + st * HG_STAGE + stDst;
        cp16(d,         aHg + k0); cp16(d + 16,         aHg + k0 + 8);
        cp16(d + 10240, bHg + k0); cp16(d + 10240 + 16, bHg + k0 + 8);
        asm volatile("cp.async.commit_group;\n");
    };

    float acc[2][8][4];
#pragma unroll
    for (int i = 0; i < 2; i++)
#pragma unroll
        for (int j = 0; j < 8; j++)
#pragma unroll
            for (int r = 0; r < 4; r++) acc[i][j][r] = 0.f;

    const uint32_t aOff = (wm + (lane & 15)) * 80 + (lane >> 4) * 16;
    const uint32_t bOff = (wn + (lane & 15)) * 80 + (lane >> 4) * 16 + 10240;

    const int nK = K / 32;
    load_st(0, 0);

    for (int kt = 0; kt < nK; kt++) {
        asm volatile("cp.async.wait_group 0;\n");
        __syncthreads();
        if (kt + 1 < nK) load_st((kt + 1) & 1, (kt + 1) * 32);
        const uint32_t sb = smB + (kt & 1) * HG_STAGE;

#pragma unroll
        for (int s = 0; s < 2; s++) {
            uint32_t ah[2][4];
#pragma unroll
            for (int i = 0; i < 2; i++)
                ldsm4(ah[i][0], ah[i][1], ah[i][2], ah[i][3],
                      sb + aOff + i * 1280 + s * 32);
#pragma unroll
            for (int j = 0; j < 4; j++) {
                uint32_t bh_[4];
                ldsm4(bh_[0], bh_[1], bh_[2], bh_[3],
                      sb + bOff + j * 1280 + s * 32);
#pragma unroll
                for (int i = 0; i < 2; i++) {
                    mma_f16(acc[i][2*j  ], ah[i][0], ah[i][1], ah[i][2], ah[i][3], bh_[0], bh_[2]);
                    mma_f16(acc[i][2*j+1], ah[i][0], ah[i][1], ah[i][2], ah[i][3], bh_[1], bh_[3]);
                }
            }
        }
    }

#pragma unroll
    for (int i = 0; i < 2; i++) {
#pragma unroll
        for (int j = 0; j < 8; j++) {
            const int r0 = mb + wm + i * 16 + gr;
            const int c0 = nb + wn + j * 8 + 2 * tg;     // even
            const float bia0 = bias[c0], bia1 = bias[c0 + 1];
            const int tsel = c0 >> 10, rem = c0 & 1023;
            const int hh = rem >> 6, d = rem & 63;
#pragma unroll
            for (int pr = 0; pr < 2; pr++) {
                const int m = r0 + pr * 8;
                const int bb = m >> 10, s = m & 1023;
                const int bh2 = bb * NHEADS + hh;
                const float v0 = acc[i][j][pr*2 + 0] + bia0;
                const float v1 = acc[i][j][pr*2 + 1] + bia1;
                if (tsel < 2) {
                    int i0 = __float2int_rn(fminf(fmaxf(v0 * QSCALE, -127.f), 127.f));
                    int i1 = __float2int_rn(fminf(fmaxf(v1 * QSCALE, -127.f), 127.f));
                    unsigned short pk8 = (unsigned short)((i0 & 0xFF) | ((i1 & 0xFF) << 8));
                    *(unsigned short*)((char*)&g_qk8[tsel][bh2][d >> 2][s] + (d & 3)) = pk8;
                } else {
                    *(uint32_t*)&g_vh[bh2][s][d] = h2u(__floats2half2_rn(v0, v1));
                }
            }
        }
    }
}

// ==============================================================================
// fp16 GEMM (NT) for output projection, BM=128 BN=64 BK=32, 3-stage.
// Trailing barrier removed: with a 3-slot ring, stage (kt+2)%3 never aliases
// the stages read at kt or kt+1.
// ==============================================================================
#define P64_STAGE 15360
#define P64_SMEM  (3*P64_STAGE)

__global__ __launch_bounds__(256, 3) void proj64(
    const float* __restrict__ bias, float* __restrict__ C, int N, int K)
{
    extern __shared__ char smh[];
    const uint32_t smB = smem_u32(smh);

    const int tid  = threadIdx.x;
    const int warp = tid >> 5;
    const int lane = tid & 31;
    const int gr   = lane >> 2;
    const int tg   = lane & 3;
    const int wm   = (warp & 3) * 32;
    const int wn   = (warp >> 2) * 32;
    const int mb   = blockIdx.y * 128;
    const int nb   = blockIdx.x * 64;

    const int rowA = tid >> 1, cpA = (tid & 1) * 2;
    const int rowB = tid >> 2, chB = tid & 3;
    const __half* aHg = g_yh  + (size_t)(mb + rowA) * K + cpA * 8;
    const __half* bHg = g_wph + (size_t)(nb + rowB) * K + chB * 8;
    const uint32_t stA = rowA * 80 + cpA * 16;
    const uint32_t stB = 10240 + rowB * 80 + chB * 16;

    auto load_st = [&](int st, int k0) {
        const uint32_t d = smB + st * P64_STAGE;
        cp16(d + stA,      aHg + k0);
        cp16(d + stA + 16, aHg + k0 + 8);
        cp16(d + stB,      bHg + k0);
        asm volatile("cp.async.commit_group;\n");
    };

    float acc[2][4][4];
#pragma unroll
    for (int i = 0; i < 2; i++)
#pragma unroll
        for (int j = 0; j < 4; j++)
#pragma unroll
            for (int r = 0; r < 4; r++) acc[i][j][r] = 0.f;

    const uint32_t aOff = (wm + (lane & 15)) * 80 + (lane >> 4) * 16;
    const uint32_t bOff = 10240 + (wn + (lane & 15)) * 80 + (lane >> 4) * 16;

    const int nK = K / 32;
    load_st(0, 0);
    load_st(1, 32);

    for (int kt = 0; kt < nK; kt++) {
        asm volatile("cp.async.wait_group 1;\n");
        __syncthreads();
        if (kt + 2 < nK) load_st((kt + 2) % 3, (kt + 2) * 32);
        const uint32_t sb = smB + (kt % 3) * P64_STAGE;

#pragma unroll
        for (int s = 0; s < 2; s++) {
            uint32_t ah[2][4];
#pragma unroll
            for (int i = 0; i < 2; i++)
                ldsm4(ah[i][0], ah[i][1], ah[i][2], ah[i][3],
                      sb + aOff + i * 1280 + s * 32);
#pragma unroll
            for (int j = 0; j < 2; j++) {
                uint32_t bh_[4];
                ldsm4(bh_[0], bh_[1], bh_[2], bh_[3],
                      sb + bOff + j * 1280 + s * 32);
#pragma unroll
                for (int i = 0; i < 2; i++) {
                    mma_f16(acc[i][2*j  ], ah[i][0], ah[i][1], ah[i][2], ah[i][3], bh_[0], bh_[2]);
                    mma_f16(acc[i][2*j+1], ah[i][0], ah[i][1], ah[i][2], ah[i][3], bh_[1], bh_[3]);
                }
            }
        }
    }

#pragma unroll
    for (int i = 0; i < 2; i++) {
#pragma unroll
        for (int j = 0; j < 4; j++) {
            const int r0 = mb + wm + i * 16 + gr;
            const int c0 = nb + wn + j * 8 + 2 * tg;
            const float bia0 = bias[c0], bia1 = bias[c0 + 1];
            float2 lo = make_float2(acc[i][j][0] + bia0, acc[i][j][1] + bia1);
            float2 hi = make_float2(acc[i][j][2] + bia0, acc[i][j][3] + bia1);
            *(float2*)&C[(size_t)r0 * N + c0]       = lo;
            *(float2*)&C[(size_t)(r0 + 8) * N + c0] = hi;
        }
    }
}

// ==============================================================================
// FUSED Laplacian (int8 SIMD dist + ex2.f16x2) + attn@v + rownorm + dwc (fp16 v).
// ==============================================================================
#define QS_OFF   0
#define KS_OFF   4352
#define KT_OFF   13056
#define VH_OFF   22272
#define RS_OFF   40704
#define LAP_SMEM 40960

__global__ __launch_bounds__(256, 3) void lap_av(const float* __restrict__ dwc_w,
                                                 const float* __restrict__ dwc_b)
{
    extern __shared__ char sm[];
    const uint32_t smB = smem_u32(sm);

    const int tid  = threadIdx.x;
    const int tx   = tid & 15;
    const int ty   = tid >> 4;
    const int warp = tid >> 5;
    const int lane = tid & 31;
    const int gr   = lane >> 2;
    const int tg   = lane & 3;
    const int wm4  = (warp & 3) * 16;
    const int wn2  = (warp >> 2) * 32;
    const int it   = blockIdx.x;
    const int bh   = blockIdx.y;
    const int bb   = bh >> 4;
    const int h    = bh & 15;

    const char* Q8 = (const char*)&g_qk8[0][bh][0][0];
    const char* K8 = (const char*)&g_qk8[1][bh][0][0];
    const __half* Vh = &g_vh[bh][0][0];

    const int d4s = tid >> 4, cs = tid & 15;

    auto stage_q = [&]() {
        cp16(smB + QS_OFF + d4s * 272 + cs * 16,
             Q8 + (size_t)d4s * 4096 + (size_t)it * 256 + cs * 16);
    };
    auto stage_k = [&](int buf, int jt) {
        cp16(smB + KS_OFF + buf * 4352 + d4s * 272 + cs * 16,
             K8 + (size_t)d4s * 4096 + (size_t)jt * 256 + cs * 16);
    };
    auto stage_v = [&](int buf, int jt) {
#pragma unroll
        for (int r = 0; r < 2; r++) {
            int idx = tid + r * 256;
            int j = idx >> 3, c = idx & 7;
            cp16(smB + VH_OFF + buf * 9216 + j * 144 + c * 16,
                 (const char*)Vh + ((size_t)(jt * 64 + j) * 64 + c * 8) * 2);
        }
    };

    const uint32_t aKt = smB + KT_OFF
        + (wm4 + (lane & 7) + ((lane >> 3) & 1) * 8) * 144 + (lane >> 4) * 16;
    const uint32_t bVh = smB + VH_OFF
        + (lane & 15) * 144 + (lane >> 4) * 16 + wn2 * 2;

    stage_q(); stage_k(0, 0); stage_v(0, 0);
    asm volatile("cp.async.commit_group;\n");

    float rs[4] = {0.f, 0.f, 0.f, 0.f};
    float macc[4][4];
#pragma unroll
    for (int n = 0; n < 4; n++)
#pragma unroll
        for (int e = 0; e < 4; e++) macc[n][e] = 0.f;

    const uint32_t* qsP = (const uint32_t*)(sm + QS_OFF);

    for (int jt = 0; jt < 16; jt++) {
        const int buf = jt & 1;
        asm volatile("cp.async.wait_group 0;\n");
        __syncthreads();
        if (jt < 15) {
            stage_k(buf ^ 1, jt + 1);
            stage_v(buf ^ 1, jt + 1);
            asm volatile("cp.async.commit_group;\n");
        }

        // ---- dist phase: int8 SIMD (vabsdiff4 + dp4a) ----
        const uint32_t* ksP = (const uint32_t*)(sm + KS_OFF + buf * 4352);
        unsigned acc[4][4];
#pragma unroll
        for (int ii = 0; ii < 4; ii++)
#pragma unroll
            for (int jj = 0; jj < 4; jj++) acc[ii][jj] = 0u;

#pragma unroll
        for (int d4 = 0; d4 < 16; d4++) {
            uint4 qv = *(const uint4*)(qsP + d4 * 68 + ty * 4);
            uint4 kv = *(const uint4*)(ksP + d4 * 68 + tx * 4);
            uint32_t q2[4] = {qv.x, qv.y, qv.z, qv.w};
            uint32_t k2[4] = {kv.x, kv.y, kv.z, kv.w};
#pragma unroll
            for (int ii = 0; ii < 4; ii++)
#pragma unroll
                for (int jj = 0; jj < 4; jj++)
                    acc[ii][jj] = __dp4a(__vabsdiffs4(q2[ii], k2[jj]),
                                         0x01010101u, acc[ii][jj]);
        }

        // ---- kern tile: ex2.approx.f16x2 ----
#pragma unroll
        for (int ii = 0; ii < 4; ii++) {
            float a0 = (float)acc[ii][0] * C2F;
            float a1 = (float)acc[ii][1] * C2F;
            float a2 = (float)acc[ii][2] * C2F;
            float a3 = (float)acc[ii][3] * C2F;
            uint32_t k01 = ex2_h2(a0, a1);
            uint32_t k23 = ex2_h2(a2, a3);
            *(uint2*)(sm + KT_OFF + (ty*4 + ii) * 144 + tx * 8)
                = make_uint2(k01, k23);
            float2 fr = __half22float2(__hadd2(u2h(k01), u2h(k23)));
            rs[ii] += fr.x + fr.y;
        }
        __syncthreads();

        // ---- mma phase: macc += kt @ vh[buf] ----
        const uint32_t bB = bVh + buf * 9216;
#pragma unroll
        for (int k16 = 0; k16 < 4; k16++) {
            uint32_t a0, a1, a2, a3;
            ldsm4(a0, a1, a2, a3, aKt + k16 * 32);
#pragma unroll
            for (int nf2 = 0; nf2 < 2; nf2++) {
                uint32_t b0, b1, b2, b3;
                ldsm4t(b0, b1, b2, b3, bB + k16 * 2304 + nf2 * 32);
                mma_f16(macc[2*nf2    ], a0, a1, a2, a3, b0, b1);
                mma_f16(macc[2*nf2 + 1], a0, a1, a2, a3, b2, b3);
            }
        }
    }

    float* rsum = (float*)(sm + RS_OFF);
#pragma unroll
    for (int ii = 0; ii < 4; ii++) {
        float v = rs[ii];
        v += __shfl_xor_sync(0xffffffffu, v, 1);
        v += __shfl_xor_sync(0xffffffffu, v, 2);
        v += __shfl_xor_sync(0xffffffffu, v, 4);
        v += __shfl_xor_sync(0xffffffffu, v, 8);
        if (tx == 0) rsum[ty*4 + ii] = v;
    }
    __syncthreads();

#pragma unroll
    for (int nf = 0; nf < 4; nf++) {
        const int dl = wn2 + nf * 8 + tg * 2;
        const int c  = h * 64 + dl;
        const float w0a = dwc_w[c*3+0], w1a = dwc_w[c*3+1], w2a = dwc_w[c*3+2];
        const float b0a = dwc_b[c];
        const float w0b = dwc_w[c*3+3], w1b = dwc_w[c*3+4], w2b = dwc_w[c*3+5];
        const float b1b = dwc_b[c+1];
#pragma unroll
        for (int half = 0; half < 2; half++) {
            const int il = wm4 + gr + half * 8;
            const int s  = it * 64 + il;
            const float sc = 1.0f / (rsum[il] + 1e-6f);
            float o0 = macc[nf][half*2 + 0] * sc;
            float o1 = macc[nf][half*2 + 1] * sc;
            float2 v0 = __half22float2(*(const __half2*)&Vh[(size_t)s*64 + dl]);
            float2 vm = (s > 0)
                ? __half22float2(*(const __half2*)&Vh[(size_t)(s-1)*64 + dl])
                : make_float2(0.f, 0.f);
            float2 vp = (s < SEQ - 1)
                ? __half22float2(*(const __half2*)&Vh[(size_t)(s+1)*64 + dl])
                : make_float2(0.f, 0.f);
            o0 += w0a*vm.x + w1a*v0.x + w2a*vp.x + b0a;
            o1 += w0b*vm.y + w1b*v0.y + w2b*vp.y + b1b;
            const size_t oidx = (size_t)(bb*SEQ + s) * 1024 + c;
            *(uint32_t*)&g_yh[oidx] = h2u(__floats2half2_rn(o0, o1));
        }
    }
}

// ==============================================================================
extern "C" void kernel_launch(void* const* d_in, const int* in_sizes, int n_in,
                              void* d_out, int out_size)
{
    const float* x      = (const float*)d_in[0];
    const float* qkv_w  = (const float*)d_in[1];
    const float* qkv_b  = (const float*)d_in[2];
    const float* proj_w = (const float*)d_in[3];
    const float* proj_b = (const float*)d_in[4];
    const float* dwc_w  = (const float*)d_in[5];
    const float* dwc_b  = (const float*)d_in[6];
    float* out = (float*)d_out;

    cudaFuncSetAttribute(hgemm_qkv, cudaFuncAttributeMaxDynamicSharedMemorySize, HG_SMEM);
    cudaFuncSetAttribute(proj64,    cudaFuncAttributeMaxDynamicSharedMemorySize, P64_SMEM);
    cudaFuncSetAttribute(lap_av,    cudaFuncAttributeMaxDynamicSharedMemorySize, LAP_SMEM);

    // 0) convert x / weights to fp16 scratch
    prep_f16<<<dim3(3072, 3), 256>>>(x, qkv_w, proj_w);
    // 1) qkv projection (fp16 HMMA); q,k -> int8 packed, v -> fp16
    hgemm_qkv<<<dim3(24, 16), 256, HG_SMEM>>>(qkv_b, 3072, 1024);
    // 2) FUSED Laplacian (int8 dist + ex2.f16x2) + attn@v + rownorm + dwc -> y
    lap_av<<<dim3(16, 32), 256, LAP_SMEM>>>(dwc_w, dwc_b);
    // 3) output projection (fp16 HMMA, BN=64, 3-stage, no trailing bar) -> d_out
    proj64<<<dim3(16, 16), 256, P64_SMEM>>>(proj_b, out, 1024, 1024);
}

// round 17
// speedup vs baseline: 1.5771x; 1.0217x over previous
#include <cuda_runtime.h>
#include <cuda_fp16.h>
#include <cstdint>

#define SEQ 1024
#define DIMC 1024
#define NHEADS 16
#define HDIM 64
#define NBATCH 2
#define NBH (NBATCH*NHEADS)   // 32

// ---------------- scratch (device globals; no runtime allocation) -------------
__device__ __half   g_vh[NBH][SEQ][HDIM];       // 4 MB  v fp16 (mma + dwc)
__device__ uint32_t g_qk8[2][NBH][16][1024];    // 4 MB  q,k int8x4: [d4][s]
__device__ __half   g_xh[2048*1024];            // fp16 x
__device__ __half   g_wqh[3072*1024];           // fp16 qkv_w
__device__ __half   g_wph[1024*1024];           // fp16 proj_w
__device__ __half   g_yh[2048*1024];            // fp16 pre-projection activations

#define QSCALE  32.0f
// ex2 coefficient: -LAMBDA/HEAD_DIM/QSCALE * log2(e) = -0.0625/32 * 1.4426950
#define C2F     (-2.8177637e-3f)

// ---------------- helpers ------------------------------------------------------
__device__ __forceinline__ uint32_t smem_u32(const void* p) {
    return (uint32_t)__cvta_generic_to_shared(p);
}
__device__ __forceinline__ void cp16(uint32_t s, const void* g) {
    asm volatile("cp.async.cg.shared.global [%0], [%1], 16;\n" :: "r"(s), "l"(g));
}
__device__ __forceinline__ void mma_f16(float c[4],
        uint32_t a0, uint32_t a1, uint32_t a2, uint32_t a3,
        uint32_t b0, uint32_t b1) {
    asm volatile(
        "mma.sync.aligned.m16n8k16.row.col.f32.f16.f16.f32 "
        "{%0,%1,%2,%3}, {%4,%5,%6,%7}, {%8,%9}, {%0,%1,%2,%3};"
        : "+f"(c[0]), "+f"(c[1]), "+f"(c[2]), "+f"(c[3])
        : "r"(a0), "r"(a1), "r"(a2), "r"(a3), "r"(b0), "r"(b1));
}
__device__ __forceinline__ void ldsm4(uint32_t& r0, uint32_t& r1,
                                      uint32_t& r2, uint32_t& r3, uint32_t a) {
    asm volatile("ldmatrix.sync.aligned.m8n8.x4.shared.b16 {%0,%1,%2,%3}, [%4];"
                 : "=r"(r0), "=r"(r1), "=r"(r2), "=r"(r3) : "r"(a));
}
__device__ __forceinline__ void ldsm4t(uint32_t& r0, uint32_t& r1,
                                       uint32_t& r2, uint32_t& r3, uint32_t a) {
    asm volatile("ldmatrix.sync.aligned.m8n8.x4.trans.shared.b16 {%0,%1,%2,%3}, [%4];"
                 : "=r"(r0), "=r"(r1), "=r"(r2), "=r"(r3) : "r"(a));
}
__device__ __forceinline__ uint32_t h2u(__half2 h) { return *(uint32_t*)&h; }
__device__ __forceinline__ __half2 u2h(uint32_t u) { return *(__half2*)&u; }
// pack two f32 into f16x2 (lo = a0, hi = a1), then 2^x on both halves
__device__ __forceinline__ uint32_t ex2_h2(float a0, float a1) {
    uint32_t p, r;
    asm("cvt.rn.f16x2.f32 %0, %1, %2;" : "=r"(p) : "f"(a1), "f"(a0));
    asm("ex2.approx.f16x2 %0, %1;" : "=r"(r) : "r"(p));
    return r;
}

// ==============================================================================
// Prepass: convert x / qkv_w / proj_w to fp16 scratch copies.
// ==============================================================================
__global__ __launch_bounds__(256) void prep_f16(const float* __restrict__ x,
                                                const float* __restrict__ wq,
                                                const float* __restrict__ wp)
{
    const float4* src; __half* dh; int n4;
    if (blockIdx.y == 0)      { src = (const float4*)x;  dh = g_xh;  n4 = 524288; }
    else if (blockIdx.y == 1) { src = (const float4*)wq; dh = g_wqh; n4 = 786432; }
    else                      { src = (const float4*)wp; dh = g_wph; n4 = 262144; }
    int i = blockIdx.x * 256 + threadIdx.x;
    if (i < n4) {
        float4 v = src[i];
        ((uint2*)dh)[i] = make_uint2(h2u(__floats2half2_rn(v.x, v.y)),
                                     h2u(__floats2half2_rn(v.z, v.w)));
    }
}

// ==============================================================================
// fp16 GEMM (NT) for qkv: BM=64 BN=128 BK=32, 2-stage, occ 3 (wave-balanced).
// 8 warps = 2M x 4N, warp tile 32x32.
// A=x, B=qkv_w; q,k -> g_qk8 (int8 packed, QSCALE), v -> g_vh.
// stage: A 64x80B (5120) | B 128x80B (10240) = 15360; x2 stages.
// ==============================================================================
#define QK_STAGE 15360
#define QK_SMEM  (2*QK_STAGE)

__global__ __launch_bounds__(256, 3) void hgemm_qkv(
    const float* __restrict__ bias, int N, int K)
{
    extern __shared__ char smh[];
    const uint32_t smB = smem_u32(smh);

    const int tid  = threadIdx.x;
    const int warp = tid >> 5;
    const int lane = tid & 31;
    const int gr   = lane >> 2;
    const int tg   = lane & 3;
    const int wm   = (warp & 1) * 32;     // 2 warps in M
    const int wn   = (warp >> 1) * 32;    // 4 warps in N
    const int mb   = blockIdx.y * 64;
    const int nb   = blockIdx.x * 128;

    // staging coords
    const int rowA = tid >> 2, chA = tid & 3;           // A: 1 chunk/thread
    const int rowB = tid >> 2, chB = tid & 3;           // B: 2 chunks/thread
    const __half* aHg = g_xh  + (size_t)(mb + rowA) * K + chA * 8;
    const __half* bHg = g_wqh + (size_t)(nb + rowB) * K + chB * 8;
    const uint32_t stA = rowA * 80 + chA * 16;
    const uint32_t stB = 5120 + rowB * 80 + chB * 16;

    auto load_st = [&](int st, int k0) {
        const uint32_t d = smB + st * QK_STAGE;
        cp16(d + stA,             aHg + k0);
        cp16(d + stB,             bHg + k0);
        cp16(d + stB + 64 * 80,   bHg + (size_t)64 * K + k0);
        asm volatile("cp.async.commit_group;\n");
    };

    float acc[2][4][4];
#pragma unroll
    for (int i = 0; i < 2; i++)
#pragma unroll
        for (int j = 0; j < 4; j++)
#pragma unroll
            for (int r = 0; r < 4; r++) acc[i][j][r] = 0.f;

    const uint32_t aOff = (wm + (lane & 15)) * 80 + (lane >> 4) * 16;
    const uint32_t bOff = 5120 + (wn + (lane & 15)) * 80 + (lane >> 4) * 16;

    const int nK = K / 32;
    load_st(0, 0);

    for (int kt = 0; kt < nK; kt++) {
        asm volatile("cp.async.wait_group 0;\n");
        __syncthreads();
        if (kt + 1 < nK) load_st((kt + 1) & 1, (kt + 1) * 32);
        const uint32_t sb = smB + (kt & 1) * QK_STAGE;

#pragma unroll
        for (int s = 0; s < 2; s++) {
            uint32_t ah[2][4];
#pragma unroll
            for (int i = 0; i < 2; i++)
                ldsm4(ah[i][0], ah[i][1], ah[i][2], ah[i][3],
                      sb + aOff + i * 1280 + s * 32);
#pragma unroll
            for (int j = 0; j < 2; j++) {
                uint32_t bh_[4];
                ldsm4(bh_[0], bh_[1], bh_[2], bh_[3],
                      sb + bOff + j * 1280 + s * 32);
#pragma unroll
                for (int i = 0; i < 2; i++) {
                    mma_f16(acc[i][2*j  ], ah[i][0], ah[i][1], ah[i][2], ah[i][3], bh_[0], bh_[2]);
                    mma_f16(acc[i][2*j+1], ah[i][0], ah[i][1], ah[i][2], ah[i][3], bh_[1], bh_[3]);
                }
            }
        }
    }

#pragma unroll
    for (int i = 0; i < 2; i++) {
#pragma unroll
        for (int j = 0; j < 4; j++) {
            const int r0 = mb + wm + i * 16 + gr;
            const int c0 = nb + wn + j * 8 + 2 * tg;     // even
            const float bia0 = bias[c0], bia1 = bias[c0 + 1];
            const int tsel = c0 >> 10, rem = c0 & 1023;
            const int hh = rem >> 6, d = rem & 63;
#pragma unroll
            for (int pr = 0; pr < 2; pr++) {
                const int m = r0 + pr * 8;
                const int bb = m >> 10, s = m & 1023;
                const int bh2 = bb * NHEADS + hh;
                const float v0 = acc[i][j][pr*2 + 0] + bia0;
                const float v1 = acc[i][j][pr*2 + 1] + bia1;
                if (tsel < 2) {
                    int i0 = __float2int_rn(fminf(fmaxf(v0 * QSCALE, -127.f), 127.f));
                    int i1 = __float2int_rn(fminf(fmaxf(v1 * QSCALE, -127.f), 127.f));
                    unsigned short pk8 = (unsigned short)((i0 & 0xFF) | ((i1 & 0xFF) << 8));
                    *(unsigned short*)((char*)&g_qk8[tsel][bh2][d >> 2][s] + (d & 3)) = pk8;
                } else {
                    *(uint32_t*)&g_vh[bh2][s][d] = h2u(__floats2half2_rn(v0, v1));
                }
            }
        }
    }
}

// ==============================================================================
// fp16 GEMM (NT) for output projection, BM=128 BN=64 BK=32, 3-stage (proven).
// ==============================================================================
#define P64_STAGE 15360
#define P64_SMEM  (3*P64_STAGE)

__global__ __launch_bounds__(256, 3) void proj64(
    const float* __restrict__ bias, float* __restrict__ C, int N, int K)
{
    extern __shared__ char smh[];
    const uint32_t smB = smem_u32(smh);

    const int tid  = threadIdx.x;
    const int warp = tid >> 5;
    const int lane = tid & 31;
    const int gr   = lane >> 2;
    const int tg   = lane & 3;
    const int wm   = (warp & 3) * 32;
    const int wn   = (warp >> 2) * 32;
    const int mb   = blockIdx.y * 128;
    const int nb   = blockIdx.x * 64;

    const int rowA = tid >> 1, cpA = (tid & 1) * 2;
    const int rowB = tid >> 2, chB = tid & 3;
    const __half* aHg = g_yh  + (size_t)(mb + rowA) * K + cpA * 8;
    const __half* bHg = g_wph + (size_t)(nb + rowB) * K + chB * 8;
    const uint32_t stA = rowA * 80 + cpA * 16;
    const uint32_t stB = 10240 + rowB * 80 + chB * 16;

    auto load_st = [&](int st, int k0) {
        const uint32_t d = smB + st * P64_STAGE;
        cp16(d + stA,      aHg + k0);
        cp16(d + stA + 16, aHg + k0 + 8);
        cp16(d + stB,      bHg + k0);
        asm volatile("cp.async.commit_group;\n");
    };

    float acc[2][4][4];
#pragma unroll
    for (int i = 0; i < 2; i++)
#pragma unroll
        for (int j = 0; j < 4; j++)
#pragma unroll
            for (int r = 0; r < 4; r++) acc[i][j][r] = 0.f;

    const uint32_t aOff = (wm + (lane & 15)) * 80 + (lane >> 4) * 16;
    const uint32_t bOff = 10240 + (wn + (lane & 15)) * 80 + (lane >> 4) * 16;

    const int nK = K / 32;
    load_st(0, 0);
    load_st(1, 32);

    for (int kt = 0; kt < nK; kt++) {
        asm volatile("cp.async.wait_group 1;\n");
        __syncthreads();
        if (kt + 2 < nK) load_st((kt + 2) % 3, (kt + 2) * 32);
        const uint32_t sb = smB + (kt % 3) * P64_STAGE;

#pragma unroll
        for (int s = 0; s < 2; s++) {
            uint32_t ah[2][4];
#pragma unroll
            for (int i = 0; i < 2; i++)
                ldsm4(ah[i][0], ah[i][1], ah[i][2], ah[i][3],
                      sb + aOff + i * 1280 + s * 32);
#pragma unroll
            for (int j = 0; j < 2; j++) {
                uint32_t bh_[4];
                ldsm4(bh_[0], bh_[1], bh_[2], bh_[3],
                      sb + bOff + j * 1280 + s * 32);
#pragma unroll
                for (int i = 0; i < 2; i++) {
                    mma_f16(acc[i][2*j  ], ah[i][0], ah[i][1], ah[i][2], ah[i][3], bh_[0], bh_[2]);
                    mma_f16(acc[i][2*j+1], ah[i][0], ah[i][1], ah[i][2], ah[i][3], bh_[1], bh_[3]);
                }
            }
        }
    }

#pragma unroll
    for (int i = 0; i < 2; i++) {
#pragma unroll
        for (int j = 0; j < 4; j++) {
            const int r0 = mb + wm + i * 16 + gr;
            const int c0 = nb + wn + j * 8 + 2 * tg;
            const float bia0 = bias[c0], bia1 = bias[c0 + 1];
            float2 lo = make_float2(acc[i][j][0] + bia0, acc[i][j][1] + bia1);
            float2 hi = make_float2(acc[i][j][2] + bia0, acc[i][j][3] + bia1);
            *(float2*)&C[(size_t)r0 * N + c0]       = lo;
            *(float2*)&C[(size_t)(r0 + 8) * N + c0] = hi;
        }
    }
}

// ==============================================================================
// FUSED Laplacian (int8 SIMD dist + ex2.f16x2) + attn@v + rownorm + dwc.
// occ 4 -> 512 CTAs in a SINGLE wave (was 2 waves at occ 3).
// ==============================================================================
#define QS_OFF   0
#define KS_OFF   4352
#define KT_OFF   13056
#define VH_OFF   22272
#define RS_OFF   40704
#define LAP_SMEM 40960

__global__ __launch_bounds__(256, 4) void lap_av(const float* __restrict__ dwc_w,
                                                 const float* __restrict__ dwc_b)
{
    extern __shared__ char sm[];
    const uint32_t smB = smem_u32(sm);

    const int tid  = threadIdx.x;
    const int tx   = tid & 15;
    const int ty   = tid >> 4;
    const int warp = tid >> 5;
    const int lane = tid & 31;
    const int gr   = lane >> 2;
    const int tg   = lane & 3;
    const int wm4  = (warp & 3) * 16;
    const int wn2  = (warp >> 2) * 32;
    const int it   = blockIdx.x;
    const int bh   = blockIdx.y;
    const int bb   = bh >> 4;
    const int h    = bh & 15;

    const char* Q8 = (const char*)&g_qk8[0][bh][0][0];
    const char* K8 = (const char*)&g_qk8[1][bh][0][0];
    const __half* Vh = &g_vh[bh][0][0];

    const int d4s = tid >> 4, cs = tid & 15;

    auto stage_q = [&]() {
        cp16(smB + QS_OFF + d4s * 272 + cs * 16,
             Q8 + (size_t)d4s * 4096 + (size_t)it * 256 + cs * 16);
    };
    auto stage_k = [&](int buf, int jt) {
        cp16(smB + KS_OFF + buf * 4352 + d4s * 272 + cs * 16,
             K8 + (size_t)d4s * 4096 + (size_t)jt * 256 + cs * 16);
    };
    auto stage_v = [&](int buf, int jt) {
#pragma unroll
        for (int r = 0; r < 2; r++) {
            int idx = tid + r * 256;
            int j = idx >> 3, c = idx & 7;
            cp16(smB + VH_OFF + buf * 9216 + j * 144 + c * 16,
                 (const char*)Vh + ((size_t)(jt * 64 + j) * 64 + c * 8) * 2);
        }
    };

    const uint32_t aKt = smB + KT_OFF
        + (wm4 + (lane & 7) + ((lane >> 3) & 1) * 8) * 144 + (lane >> 4) * 16;
    const uint32_t bVh = smB + VH_OFF
        + (lane & 15) * 144 + (lane >> 4) * 16 + wn2 * 2;

    stage_q(); stage_k(0, 0); stage_v(0, 0);
    asm volatile("cp.async.commit_group;\n");

    float rs[4] = {0.f, 0.f, 0.f, 0.f};
    float macc[4][4];
#pragma unroll
    for (int n = 0; n < 4; n++)
#pragma unroll
        for (int e = 0; e < 4; e++) macc[n][e] = 0.f;

    const uint32_t* qsP = (const uint32_t*)(sm + QS_OFF);

    for (int jt = 0; jt < 16; jt++) {
        const int buf = jt & 1;
        asm volatile("cp.async.wait_group 0;\n");
        __syncthreads();
        if (jt < 15) {
            stage_k(buf ^ 1, jt + 1);
            stage_v(buf ^ 1, jt + 1);
            asm volatile("cp.async.commit_group;\n");
        }

        // ---- dist phase: int8 SIMD (vabsdiff4 + dp4a) ----
        const uint32_t* ksP = (const uint32_t*)(sm + KS_OFF + buf * 4352);
        unsigned acc[4][4];
#pragma unroll
        for (int ii = 0; ii < 4; ii++)
#pragma unroll
            for (int jj = 0; jj < 4; jj++) acc[ii][jj] = 0u;

#pragma unroll
        for (int d4 = 0; d4 < 16; d4++) {
            uint4 qv = *(const uint4*)(qsP + d4 * 68 + ty * 4);
            uint4 kv = *(const uint4*)(ksP + d4 * 68 + tx * 4);
            uint32_t q2[4] = {qv.x, qv.y, qv.z, qv.w};
            uint32_t k2[4] = {kv.x, kv.y, kv.z, kv.w};
#pragma unroll
            for (int ii = 0; ii < 4; ii++)
#pragma unroll
                for (int jj = 0; jj < 4; jj++)
                    acc[ii][jj] = __dp4a(__vabsdiffs4(q2[ii], k2[jj]),
                                         0x01010101u, acc[ii][jj]);
        }

        // ---- kern tile: ex2.approx.f16x2 ----
#pragma unroll
        for (int ii = 0; ii < 4; ii++) {
            float a0 = (float)acc[ii][0] * C2F;
            float a1 = (float)acc[ii][1] * C2F;
            float a2 = (float)acc[ii][2] * C2F;
            float a3 = (float)acc[ii][3] * C2F;
            uint32_t k01 = ex2_h2(a0, a1);
            uint32_t k23 = ex2_h2(a2, a3);
            *(uint2*)(sm + KT_OFF + (ty*4 + ii) * 144 + tx * 8)
                = make_uint2(k01, k23);
            float2 fr = __half22float2(__hadd2(u2h(k01), u2h(k23)));
            rs[ii] += fr.x + fr.y;
        }
        __syncthreads();

        // ---- mma phase: macc += kt @ vh[buf] ----
        const uint32_t bB = bVh + buf * 9216;
#pragma unroll
        for (int k16 = 0; k16 < 4; k16++) {
            uint32_t a0, a1, a2, a3;
            ldsm4(a0, a1, a2, a3, aKt + k16 * 32);
#pragma unroll
            for (int nf2 = 0; nf2 < 2; nf2++) {
                uint32_t b0, b1, b2, b3;
                ldsm4t(b0, b1, b2, b3, bB + k16 * 2304 + nf2 * 32);
                mma_f16(macc[2*nf2    ], a0, a1, a2, a3, b0, b1);
                mma_f16(macc[2*nf2 + 1], a0, a1, a2, a3, b2, b3);
            }
        }
    }

    float* rsum = (float*)(sm + RS_OFF);
#pragma unroll
    for (int ii = 0; ii < 4; ii++) {
        float v = rs[ii];
        v += __shfl_xor_sync(0xffffffffu, v, 1);
        v += __shfl_xor_sync(0xffffffffu, v, 2);
        v += __shfl_xor_sync(0xffffffffu, v, 4);
        v += __shfl_xor_sync(0xffffffffu, v, 8);
        if (tx == 0) rsum[ty*4 + ii] = v;
    }
    __syncthreads();

#pragma unroll
    for (int nf = 0; nf < 4; nf++) {
        const int dl = wn2 + nf * 8 + tg * 2;
        const int c  = h * 64 + dl;
        const float w0a = dwc_w[c*3+0], w1a = dwc_w[c*3+1], w2a = dwc_w[c*3+2];
        const float b0a = dwc_b[c];
        const float w0b = dwc_w[c*3+3], w1b = dwc_w[c*3+4], w2b = dwc_w[c*3+5];
        const float b1b = dwc_b[c+1];
#pragma unroll
        for (int half = 0; half < 2; half++) {
            const int il = wm4 + gr + half * 8;
            const int s  = it * 64 + il;
            const float sc = 1.0f / (rsum[il] + 1e-6f);
            float o0 = macc[nf][half*2 + 0] * sc;
            float o1 = macc[nf][half*2 + 1] * sc;
            float2 v0 = __half22float2(*(const __half2*)&Vh[(size_t)s*64 + dl]);
            float2 vm = (s > 0)
                ? __half22float2(*(const __half2*)&Vh[(size_t)(s-1)*64 + dl])
                : make_float2(0.f, 0.f);
            float2 vp = (s < SEQ - 1)
                ? __half22float2(*(const __half2*)&Vh[(size_t)(s+1)*64 + dl])
                : make_float2(0.f, 0.f);
            o0 += w0a*vm.x + w1a*v0.x + w2a*vp.x + b0a;
            o1 += w0b*vm.y + w1b*v0.y + w2b*vp.y + b1b;
            const size_t oidx = (size_t)(bb*SEQ + s) * 1024 + c;
            *(uint32_t*)&g_yh[oidx] = h2u(__floats2half2_rn(o0, o1));
        }
    }
}

// ==============================================================================
extern "C" void kernel_launch(void* const* d_in, const int* in_sizes, int n_in,
                              void* d_out, int out_size)
{
    const float* x      = (const float*)d_in[0];
    const float* qkv_w  = (const float*)d_in[1];
    const float* qkv_b  = (const float*)d_in[2];
    const float* proj_w = (const float*)d_in[3];
    const float* proj_b = (const float*)d_in[4];
    const float* dwc_w  = (const float*)d_in[5];
    const float* dwc_b  = (const float*)d_in[6];
    float* out = (float*)d_out;

    cudaFuncSetAttribute(hgemm_qkv, cudaFuncAttributeMaxDynamicSharedMemorySize, QK_SMEM);
    cudaFuncSetAttribute(proj64,    cudaFuncAttributeMaxDynamicSharedMemorySize, P64_SMEM);
    cudaFuncSetAttribute(lap_av,    cudaFuncAttributeMaxDynamicSharedMemorySize, LAP_SMEM);

    // 0) convert x / weights to fp16 scratch
    prep_f16<<<dim3(3072, 3), 256>>>(x, qkv_w, proj_w);
    // 1) qkv projection (fp16 HMMA, BM64xBN128, occ 3); q,k -> int8, v -> fp16
    hgemm_qkv<<<dim3(24, 32), 256, QK_SMEM>>>(qkv_b, 3072, 1024);
    // 2) FUSED Laplacian (int8 dist + ex2.f16x2) + attn@v + rownorm + dwc -> y
    lap_av<<<dim3(16, 32), 256, LAP_SMEM>>>(dwc_w, dwc_b);
    // 3) output projection (fp16 HMMA, BN=64, 3-stage) -> d_out
    proj64<<<dim3(16, 16), 256, P64_SMEM>>>(proj_b, out, 1024, 1024);
}